// round 2
// baseline (speedup 1.0000x reference)
#include <cuda_runtime.h>
#include <math.h>

#define NROWS 4096      // B*T
#define CDIM  1024
#define HDIM  64
#define NHEADS 16
#define TSEQ  1024

// ---------------- scratch (static device globals: allocation-free) ----------
__device__ float g_ln1[NROWS * CDIM];
__device__ float g_q  [NROWS * CDIM];
__device__ float g_k  [NROWS * CDIM];
__device__ float g_v  [NROWS * CDIM];
__device__ float g_att[NROWS * CDIM];
__device__ float g_y  [NROWS * CDIM];
__device__ float g_ln2[NROWS * CDIM];
__device__ float g_ff [NROWS * 4 * CDIM];

// ---------------- layernorm: one block per row of 1024 ----------------------
__global__ __launch_bounds__(256) void ln_kernel(const float* __restrict__ x,
                                                 const float* __restrict__ g,
                                                 const float* __restrict__ b,
                                                 float* __restrict__ out) {
    int row = blockIdx.x;
    int t = threadIdx.x;
    const float4* xr = (const float4*)(x + (size_t)row * CDIM);
    float4 xv = xr[t];
    float s  = xv.x + xv.y + xv.z + xv.w;
    float ss = xv.x * xv.x + xv.y * xv.y + xv.z * xv.z + xv.w * xv.w;
    #pragma unroll
    for (int m = 16; m; m >>= 1) {
        s  += __shfl_xor_sync(0xffffffffu, s,  m);
        ss += __shfl_xor_sync(0xffffffffu, ss, m);
    }
    __shared__ float rs[8], rss[8];
    int warp = t >> 5, lane = t & 31;
    if (lane == 0) { rs[warp] = s; rss[warp] = ss; }
    __syncthreads();
    float tot = 0.f, tots = 0.f;
    #pragma unroll
    for (int i = 0; i < 8; i++) { tot += rs[i]; tots += rss[i]; }
    float mu  = tot * (1.0f / CDIM);
    float var = tots * (1.0f / CDIM) - mu * mu;
    float inv = rsqrtf(var + 1e-5f);
    float4 gv = ((const float4*)g)[t];
    float4 bv = ((const float4*)b)[t];
    float4 o;
    o.x = (xv.x - mu) * inv * gv.x + bv.x;
    o.y = (xv.y - mu) * inv * gv.y + bv.y;
    o.z = (xv.z - mu) * inv * gv.z + bv.z;
    o.w = (xv.w - mu) * inv * gv.w + bv.w;
    ((float4*)(out + (size_t)row * CDIM))[t] = o;
}

// ---------------- GEMM: C[M,N] = act(A[M,K] @ W[K,N] + bias) (+R) -----------
// 128x128 tile, BK=8, 256 threads, 8x8 per thread (4+4 split fragments)
__device__ __forceinline__ float gelu_exact(float v) {
    return 0.5f * v * (1.0f + erff(v * 0.70710678118654752f));
}

__global__ __launch_bounds__(256) void gemm_kernel(
    const float* __restrict__ A, const float* __restrict__ W,
    const float* __restrict__ bias, const float* __restrict__ R,
    float* __restrict__ C, int K, int N, int act) {
    __shared__ float As[8][128];
    __shared__ float Ws[8][128];
    int tid = threadIdx.x;
    int bx = blockIdx.x, by = blockIdx.y;
    int tx = tid & 15, ty = tid >> 4;

    int a_row = tid >> 1;
    int a_col = (tid & 1) * 4;
    int w_row = tid >> 5;
    int w_col = (tid & 31) * 4;

    const float* Aptr = A + (size_t)(by * 128 + a_row) * K + a_col;
    const float* Wptr = W + (size_t)w_row * N + bx * 128 + w_col;

    float acc[8][8];
    #pragma unroll
    for (int i = 0; i < 8; i++)
        #pragma unroll
        for (int j = 0; j < 8; j++) acc[i][j] = 0.f;

    for (int k0 = 0; k0 < K; k0 += 8) {
        float4 av = *(const float4*)(Aptr + k0);
        float4 wv = *(const float4*)(Wptr + (size_t)k0 * N);
        __syncthreads();
        As[a_col + 0][a_row] = av.x;
        As[a_col + 1][a_row] = av.y;
        As[a_col + 2][a_row] = av.z;
        As[a_col + 3][a_row] = av.w;
        *(float4*)&Ws[w_row][w_col] = wv;
        __syncthreads();
        #pragma unroll
        for (int kk = 0; kk < 8; kk++) {
            float4 a0 = *(const float4*)&As[kk][ty * 4];
            float4 a1 = *(const float4*)&As[kk][64 + ty * 4];
            float4 b0 = *(const float4*)&Ws[kk][tx * 4];
            float4 b1 = *(const float4*)&Ws[kk][64 + tx * 4];
            float af[8] = {a0.x, a0.y, a0.z, a0.w, a1.x, a1.y, a1.z, a1.w};
            float bf[8] = {b0.x, b0.y, b0.z, b0.w, b1.x, b1.y, b1.z, b1.w};
            #pragma unroll
            for (int i = 0; i < 8; i++)
                #pragma unroll
                for (int j = 0; j < 8; j++)
                    acc[i][j] += af[i] * bf[j];
        }
    }

    #pragma unroll
    for (int i = 0; i < 8; i++) {
        int row = by * 128 + (i >> 2) * 64 + ty * 4 + (i & 3);
        #pragma unroll
        for (int jb = 0; jb < 2; jb++) {
            int col = bx * 128 + jb * 64 + tx * 4;
            float4 bs = *(const float4*)(bias + col);
            float4 vv;
            vv.x = acc[i][jb * 4 + 0] + bs.x;
            vv.y = acc[i][jb * 4 + 1] + bs.y;
            vv.z = acc[i][jb * 4 + 2] + bs.z;
            vv.w = acc[i][jb * 4 + 3] + bs.w;
            if (act) {
                vv.x = gelu_exact(vv.x); vv.y = gelu_exact(vv.y);
                vv.z = gelu_exact(vv.z); vv.w = gelu_exact(vv.w);
            }
            if (R) {
                float4 rv = *(const float4*)(R + (size_t)row * N + col);
                vv.x += rv.x; vv.y += rv.y; vv.z += rv.z; vv.w += rv.w;
            }
            *(float4*)(C + (size_t)row * N + col) = vv;
        }
    }
}

// ---------------- fused causal flash attention ------------------------------
// grid = (T/64 query tiles, B*H). 256 threads. smem tiles 64x64 (pad 68).
#define AS 68
#define ATTN_SMEM (4 * 64 * AS * 4)

__global__ __launch_bounds__(256) void attn_kernel(const float* __restrict__ q,
                                                   const float* __restrict__ k,
                                                   const float* __restrict__ v,
                                                   float* __restrict__ o) {
    extern __shared__ float sm[];
    float* Qs = sm;
    float* Ks = Qs + 64 * AS;
    float* Vs = Ks + 64 * AS;
    float* Ss = Vs + 64 * AS;

    int qt = blockIdx.x, bh = blockIdx.y;
    int b = bh >> 4, h = bh & 15;
    int q0 = qt * 64;
    int tid = threadIdx.x;
    int wx = tid & 15, wy = tid >> 4;

    size_t base = ((size_t)b * TSEQ) * CDIM + (size_t)h * HDIM;

    #pragma unroll
    for (int i = 0; i < 16; i++) {
        int idx = i * 256 + tid;
        int r = idx >> 6, c = idx & 63;
        Qs[r * AS + c] = q[base + (size_t)(q0 + r) * CDIM + c];
    }

    float mrun[4], lrun[4], acc[4][4];
    #pragma unroll
    for (int i = 0; i < 4; i++) {
        mrun[i] = -1e30f; lrun[i] = 0.f;
        #pragma unroll
        for (int j = 0; j < 4; j++) acc[i][j] = 0.f;
    }

    for (int kt = 0; kt <= qt; kt++) {
        int k0 = kt * 64;
        __syncthreads();
        #pragma unroll
        for (int i = 0; i < 16; i++) {
            int idx = i * 256 + tid;
            int r = idx >> 6, c = idx & 63;
            size_t gidx = base + (size_t)(k0 + r) * CDIM + c;
            Ks[r * AS + c] = k[gidx];
            Vs[r * AS + c] = v[gidx];
        }
        __syncthreads();

        // S = Q @ K^T / 8 for this 64x64 tile; thread owns 4 rows x 4 keys
        float s[4][4];
        #pragma unroll
        for (int i = 0; i < 4; i++)
            #pragma unroll
            for (int j = 0; j < 4; j++) s[i][j] = 0.f;
        #pragma unroll 4
        for (int d = 0; d < 64; d += 4) {
            float4 qv[4], kv[4];
            #pragma unroll
            for (int i = 0; i < 4; i++) qv[i] = *(const float4*)&Qs[(wy * 4 + i) * AS + d];
            #pragma unroll
            for (int j = 0; j < 4; j++) kv[j] = *(const float4*)&Ks[(wx * 4 + j) * AS + d];
            #pragma unroll
            for (int i = 0; i < 4; i++)
                #pragma unroll
                for (int j = 0; j < 4; j++)
                    s[i][j] += qv[i].x * kv[j].x + qv[i].y * kv[j].y +
                               qv[i].z * kv[j].z + qv[i].w * kv[j].w;
        }
        bool diag = (kt == qt);
        #pragma unroll
        for (int i = 0; i < 4; i++)
            #pragma unroll
            for (int j = 0; j < 4; j++) {
                s[i][j] *= 0.125f;
                if (diag && (wx * 4 + j > wy * 4 + i)) s[i][j] = -1e30f;
            }

        // online softmax; row reduce across 16 lanes (same wy)
        float mt[4], lsum[4];
        #pragma unroll
        for (int i = 0; i < 4; i++)
            mt[i] = fmaxf(fmaxf(s[i][0], s[i][1]), fmaxf(s[i][2], s[i][3]));
        #pragma unroll
        for (int m = 1; m < 16; m <<= 1)
            #pragma unroll
            for (int i = 0; i < 4; i++)
                mt[i] = fmaxf(mt[i], __shfl_xor_sync(0xffffffffu, mt[i], m));
        #pragma unroll
        for (int i = 0; i < 4; i++) {
            float mnew = fmaxf(mrun[i], mt[i]);
            float corr = __expf(mrun[i] - mnew);
            mrun[i] = mnew;
            lsum[i] = 0.f;
            #pragma unroll
            for (int j = 0; j < 4; j++) {
                float p = __expf(s[i][j] - mnew);
                s[i][j] = p;
                lsum[i] += p;
            }
            #pragma unroll
            for (int j = 0; j < 4; j++) acc[i][j] *= corr;
            lrun[i] *= corr;
        }
        #pragma unroll
        for (int m = 1; m < 16; m <<= 1)
            #pragma unroll
            for (int i = 0; i < 4; i++)
                lsum[i] += __shfl_xor_sync(0xffffffffu, lsum[i], m);
        #pragma unroll
        for (int i = 0; i < 4; i++) lrun[i] += lsum[i];

        #pragma unroll
        for (int i = 0; i < 4; i++)
            *(float4*)&Ss[(wy * 4 + i) * AS + wx * 4] =
                make_float4(s[i][0], s[i][1], s[i][2], s[i][3]);
        __syncthreads();

        // O += P @ V ; thread owns 4 rows x 4 dims (dims wx*4..+3)
        #pragma unroll 4
        for (int j0 = 0; j0 < 64; j0 += 4) {
            float4 pv[4], vv[4];
            #pragma unroll
            for (int i = 0; i < 4; i++) pv[i] = *(const float4*)&Ss[(wy * 4 + i) * AS + j0];
            #pragma unroll
            for (int jj = 0; jj < 4; jj++) vv[jj] = *(const float4*)&Vs[(j0 + jj) * AS + wx * 4];
            #pragma unroll
            for (int i = 0; i < 4; i++) {
                acc[i][0] += pv[i].x * vv[0].x + pv[i].y * vv[1].x + pv[i].z * vv[2].x + pv[i].w * vv[3].x;
                acc[i][1] += pv[i].x * vv[0].y + pv[i].y * vv[1].y + pv[i].z * vv[2].y + pv[i].w * vv[3].y;
                acc[i][2] += pv[i].x * vv[0].z + pv[i].y * vv[1].z + pv[i].z * vv[2].z + pv[i].w * vv[3].z;
                acc[i][3] += pv[i].x * vv[0].w + pv[i].y * vv[1].w + pv[i].z * vv[2].w + pv[i].w * vv[3].w;
            }
        }
    }

    #pragma unroll
    for (int i = 0; i < 4; i++) {
        float invl = 1.0f / lrun[i];
        float4 ov = make_float4(acc[i][0] * invl, acc[i][1] * invl,
                                acc[i][2] * invl, acc[i][3] * invl);
        *(float4*)&o[base + (size_t)(q0 + wy * 4 + i) * CDIM + wx * 4] = ov;
    }
}

// ---------------- launch ----------------------------------------------------
extern "C" void kernel_launch(void* const* d_in, const int* in_sizes, int n_in,
                              void* d_out, int out_size) {
    const float* x   = (const float*)d_in[0];
    const float* Wq  = (const float*)d_in[1];
    const float* bq  = (const float*)d_in[2];
    const float* Wk  = (const float*)d_in[3];
    const float* bk  = (const float*)d_in[4];
    const float* Wv  = (const float*)d_in[5];
    const float* bv  = (const float*)d_in[6];
    const float* Wp  = (const float*)d_in[7];
    const float* bp  = (const float*)d_in[8];
    const float* W1  = (const float*)d_in[9];
    const float* b1  = (const float*)d_in[10];
    const float* W2  = (const float*)d_in[11];
    const float* b2  = (const float*)d_in[12];
    const float* g1  = (const float*)d_in[13];
    const float* be1 = (const float*)d_in[14];
    const float* g2  = (const float*)d_in[15];
    const float* be2 = (const float*)d_in[16];
    float* out = (float*)d_out;

    float *ln1, *qb, *kb, *vb, *att, *y, *ln2, *ff;
    cudaGetSymbolAddress((void**)&ln1, g_ln1);
    cudaGetSymbolAddress((void**)&qb,  g_q);
    cudaGetSymbolAddress((void**)&kb,  g_k);
    cudaGetSymbolAddress((void**)&vb,  g_v);
    cudaGetSymbolAddress((void**)&att, g_att);
    cudaGetSymbolAddress((void**)&y,   g_y);
    cudaGetSymbolAddress((void**)&ln2, g_ln2);
    cudaGetSymbolAddress((void**)&ff,  g_ff);

    cudaFuncSetAttribute(attn_kernel, cudaFuncAttributeMaxDynamicSharedMemorySize, ATTN_SMEM);

    dim3 gSmall(1024 / 128, NROWS / 128);   // (8, 32) for N=1024
    dim3 gBig(4096 / 128, NROWS / 128);     // (32, 32) for N=4096

    ln_kernel<<<NROWS, 256>>>(x, g1, be1, ln1);
    gemm_kernel<<<gSmall, 256>>>(ln1, Wq, bq, nullptr, qb, 1024, 1024, 0);
    gemm_kernel<<<gSmall, 256>>>(ln1, Wk, bk, nullptr, kb, 1024, 1024, 0);
    gemm_kernel<<<gSmall, 256>>>(ln1, Wv, bv, nullptr, vb, 1024, 1024, 0);
    attn_kernel<<<dim3(TSEQ / 64, 4 * NHEADS), 256, ATTN_SMEM>>>(qb, kb, vb, att);
    gemm_kernel<<<gSmall, 256>>>(att, Wp, bp, x, y, 1024, 1024, 0);
    ln_kernel<<<NROWS, 256>>>(y, g2, be2, ln2);
    gemm_kernel<<<gBig, 256>>>(ln2, W1, b1, nullptr, ff, 1024, 4096, 1);
    gemm_kernel<<<gSmall, 256>>>(ff, W2, b2, y, out, 4096, 1024, 0);
}

// round 4
// speedup vs baseline: 1.6819x; 1.6819x over previous
#include <cuda_runtime.h>
#include <cuda_bf16.h>
#include <cstdint>
#include <math.h>

#define NROWS 4096      // B*T
#define CDIM  1024
#define HDIM  64
#define NHEADS 16
#define TSEQ  1024
#define FFDIM 4096

// ================= helpers ==================================================
__device__ __forceinline__ uint32_t smem_to_u32(const void* p) {
    uint32_t a;
    asm("{ .reg .u64 t; cvta.to.shared.u64 t, %1; cvt.u32.u64 %0, t; }"
        : "=r"(a) : "l"(p));
    return a;
}
__device__ __forceinline__ void ldsm_x4(uint32_t& r0, uint32_t& r1,
                                        uint32_t& r2, uint32_t& r3, uint32_t a) {
    asm volatile("ldmatrix.sync.aligned.m8n8.x4.shared.b16 {%0,%1,%2,%3}, [%4];"
                 : "=r"(r0), "=r"(r1), "=r"(r2), "=r"(r3) : "r"(a));
}
__device__ __forceinline__ void mma_bf16(float& d0, float& d1, float& d2, float& d3,
                                         uint32_t a0, uint32_t a1, uint32_t a2, uint32_t a3,
                                         uint32_t b0, uint32_t b1) {
    asm volatile("mma.sync.aligned.m16n8k16.row.col.f32.bf16.bf16.f32 "
                 "{%0,%1,%2,%3}, {%4,%5,%6,%7}, {%8,%9}, {%0,%1,%2,%3};"
                 : "+f"(d0), "+f"(d1), "+f"(d2), "+f"(d3)
                 : "r"(a0), "r"(a1), "r"(a2), "r"(a3), "r"(b0), "r"(b1));
}
#define CP_ASYNC16(dst, src) \
    asm volatile("cp.async.cg.shared.global [%0], [%1], 16;" :: "r"(dst), "l"(src))
#define CP_COMMIT() asm volatile("cp.async.commit_group;" ::: "memory")
#define CP_WAIT0()  asm volatile("cp.async.wait_group 0;" ::: "memory")

__device__ __forceinline__ void split_bf16(float v, __nv_bfloat16& h, __nv_bfloat16& l) {
    h = __float2bfloat16(v);
    l = __float2bfloat16(v - __bfloat162float(h));
}
__device__ __forceinline__ float gelu_exact(float v) {
    return 0.5f * v * (1.0f + erff(v * 0.70710678118654752f));
}

// ================= scratch ==================================================
#define MB (1024ull * 1024ull)
__device__ __align__(1024) unsigned char g_scratch[224 * MB];
#define OFF_Q     (0 * MB)
#define OFF_K     (16 * MB)
#define OFF_V     (32 * MB)
#define OFF_Y     (48 * MB)
#define OFF_LN1H  (64 * MB)
#define OFF_LN1L  (72 * MB)
#define OFF_ATTH  (80 * MB)
#define OFF_ATTL  (88 * MB)
#define OFF_LN2H  (96 * MB)
#define OFF_LN2L  (104 * MB)
#define OFF_FFH   (112 * MB)
#define OFF_FFL   (144 * MB)
#define OFF_WQH   (176 * MB)
#define OFF_WQL   (178 * MB)
#define OFF_WKH   (180 * MB)
#define OFF_WKL   (182 * MB)
#define OFF_WVH   (184 * MB)
#define OFF_WVL   (186 * MB)
#define OFF_WPH   (188 * MB)
#define OFF_WPL   (190 * MB)
#define OFF_W1H   (192 * MB)
#define OFF_W1L   (200 * MB)
#define OFF_W2H   (208 * MB)
#define OFF_W2L   (216 * MB)

// ================= weight convert+transpose: W[K,N]f32 -> Wh/Wl[N,K]bf16 ====
__global__ __launch_bounds__(256) void wconv_kernel(const float* __restrict__ W,
                                                    __nv_bfloat16* __restrict__ Wh,
                                                    __nv_bfloat16* __restrict__ Wl,
                                                    int K, int N) {
    __shared__ float t[64][65];
    int k0 = blockIdx.x * 64, n0 = blockIdx.y * 64;
    int tid = threadIdx.x;
    #pragma unroll
    for (int i = 0; i < 16; i++) {
        int idx = i * 256 + tid;
        int r = idx >> 6, c = idx & 63;
        t[r][c] = W[(size_t)(k0 + r) * N + n0 + c];
    }
    __syncthreads();
    #pragma unroll
    for (int i = 0; i < 16; i++) {
        int idx = i * 256 + tid;
        int r = idx >> 6, c = idx & 63;
        float v = t[c][r];
        __nv_bfloat16 h, l;
        split_bf16(v, h, l);
        size_t o = (size_t)(n0 + r) * K + k0 + c;
        Wh[o] = h; Wl[o] = l;
    }
}

// ================= layernorm -> bf16 hi/lo ==================================
__global__ __launch_bounds__(256) void ln_kernel(const float* __restrict__ x,
                                                 const float* __restrict__ g,
                                                 const float* __restrict__ b,
                                                 __nv_bfloat16* __restrict__ H,
                                                 __nv_bfloat16* __restrict__ L) {
    int row = blockIdx.x;
    int t = threadIdx.x;
    const float4* xr = (const float4*)(x + (size_t)row * CDIM);
    float4 xv = xr[t];
    float s  = xv.x + xv.y + xv.z + xv.w;
    float ss = xv.x * xv.x + xv.y * xv.y + xv.z * xv.z + xv.w * xv.w;
    #pragma unroll
    for (int m = 16; m; m >>= 1) {
        s  += __shfl_xor_sync(0xffffffffu, s,  m);
        ss += __shfl_xor_sync(0xffffffffu, ss, m);
    }
    __shared__ float rs[8], rss[8];
    int warp = t >> 5, lane = t & 31;
    if (lane == 0) { rs[warp] = s; rss[warp] = ss; }
    __syncthreads();
    float tot = 0.f, tots = 0.f;
    #pragma unroll
    for (int i = 0; i < 8; i++) { tot += rs[i]; tots += rss[i]; }
    float mu  = tot * (1.0f / CDIM);
    float var = tots * (1.0f / CDIM) - mu * mu;
    float inv = rsqrtf(var + 1e-5f);
    float4 gv = ((const float4*)g)[t];
    float4 bv = ((const float4*)b)[t];
    float o0 = (xv.x - mu) * inv * gv.x + bv.x;
    float o1 = (xv.y - mu) * inv * gv.y + bv.y;
    float o2 = (xv.z - mu) * inv * gv.z + bv.z;
    float o3 = (xv.w - mu) * inv * gv.w + bv.w;
    __nv_bfloat16 h0, h1, h2, h3, l0, l1, l2, l3;
    split_bf16(o0, h0, l0); split_bf16(o1, h1, l1);
    split_bf16(o2, h2, l2); split_bf16(o3, h3, l3);
    __nv_bfloat162* Hp = (__nv_bfloat162*)(H + (size_t)row * CDIM + t * 4);
    __nv_bfloat162* Lp = (__nv_bfloat162*)(L + (size_t)row * CDIM + t * 4);
    __nv_bfloat162 a01; a01.x = h0; a01.y = h1;
    __nv_bfloat162 a23; a23.x = h2; a23.y = h3;
    __nv_bfloat162 b01; b01.x = l0; b01.y = l1;
    __nv_bfloat162 b23; b23.x = l2; b23.y = l3;
    Hp[0] = a01; Hp[1] = a23;
    Lp[0] = b01; Lp[1] = b23;
}

// ================= HMMA bf16x3 GEMM =========================================
// C[M,N] = act(A@W^T + bias) (+R). A: bf16 hi/lo [M,K]. B: bf16 hi/lo [N,K].
// 128x128 tile, BK=32, 8 warps (warp tile 32x64), cp.async double buffer.
// Smem tile: 128 rows x 80 bytes (64 data + 16 pad) -> conflict-free ldmatrix.
#define TSTR 80
#define TILE_B (128 * TSTR)        // 10240
#define BUF_B  (4 * TILE_B)        // 40960 (Ah, Al, Bh, Bl)
#define GEMM_SMEM (2 * BUF_B)      // 81920

__global__ __launch_bounds__(256) void gemm_tc(
    const __nv_bfloat16* __restrict__ Ah, const __nv_bfloat16* __restrict__ Al,
    const __nv_bfloat16* __restrict__ Bh, const __nv_bfloat16* __restrict__ Bl,
    const float* __restrict__ bias, const float* __restrict__ R,
    float* __restrict__ outF, __nv_bfloat16* __restrict__ outH,
    __nv_bfloat16* __restrict__ outL, int K, int N, int act) {
    extern __shared__ char sm[];
    uint32_t sbase = smem_to_u32(sm);
    int tid = threadIdx.x;
    int wid = tid >> 5, lane = tid & 31;
    int warp_m = wid & 3, warp_n = wid >> 2;
    int n0 = blockIdx.x * 128;
    int m0 = blockIdx.y * 128;
    int NC = K >> 5;

    float acc[2][8][4];
    #pragma unroll
    for (int i = 0; i < 2; i++)
        #pragma unroll
        for (int j = 0; j < 8; j++)
            #pragma unroll
            for (int c = 0; c < 4; c++) acc[i][j][c] = 0.f;

    const __nv_bfloat16* tiles[4] = {Ah, Al, Bh, Bl};
    int row0s[4] = {m0, m0, n0, n0};
    int ldr = tid >> 2;          // 0..63
    int ldc = tid & 3;           // 16B column

    // prologue: chunk 0 -> buf 0
    #pragma unroll
    for (int t = 0; t < 4; t++)
        #pragma unroll
        for (int it = 0; it < 2; it++) {
            int r = it * 64 + ldr;
            uint32_t dst = sbase + t * TILE_B + r * TSTR + ldc * 16;
            const __nv_bfloat16* src = tiles[t] + (size_t)(row0s[t] + r) * K + ldc * 8;
            CP_ASYNC16(dst, src);
        }
    CP_COMMIT();
    CP_WAIT0();
    __syncthreads();

    // per-lane ldmatrix base offsets
    int a_row = (lane & 7) + ((lane >> 3) & 1) * 8;     // within m-tile
    int a_kb  = ((lane >> 4) & 1) * 16;                 // k byte offset within step
    int b_row = (lane & 7) + ((lane >> 4) & 1) * 8;     // within nt-pair (16 rows)
    int b_kb  = ((lane >> 3) & 1) * 16;

    for (int kc = 0; kc < NC; kc++) {
        int b = kc & 1;
        uint32_t sbuf = sbase + b * BUF_B;
        if (kc + 1 < NC) {
            uint32_t dbuf = sbase + (b ^ 1) * BUF_B;
            int k0 = (kc + 1) * 32;
            #pragma unroll
            for (int t = 0; t < 4; t++)
                #pragma unroll
                for (int it = 0; it < 2; it++) {
                    int r = it * 64 + ldr;
                    uint32_t dst = dbuf + t * TILE_B + r * TSTR + ldc * 16;
                    const __nv_bfloat16* src = tiles[t] + (size_t)(row0s[t] + r) * K + k0 + ldc * 8;
                    CP_ASYNC16(dst, src);
                }
            CP_COMMIT();
        }

        #pragma unroll
        for (int ks = 0; ks < 2; ks++) {
            int kb = ks * 32;
            uint32_t ah[2][4], al[2][4];
            #pragma unroll
            for (int mt = 0; mt < 2; mt++) {
                uint32_t addr = sbuf + (warp_m * 32 + mt * 16 + a_row) * TSTR + kb + a_kb;
                ldsm_x4(ah[mt][0], ah[mt][1], ah[mt][2], ah[mt][3], addr);
                ldsm_x4(al[mt][0], al[mt][1], al[mt][2], al[mt][3], addr + TILE_B);
            }
            #pragma unroll
            for (int nb = 0; nb < 4; nb++) {
                uint32_t addr = sbuf + 2 * TILE_B +
                                (warp_n * 64 + nb * 16 + b_row) * TSTR + kb + b_kb;
                uint32_t bh0, bh1, bh2, bh3, bl0, bl1, bl2, bl3;
                ldsm_x4(bh0, bh1, bh2, bh3, addr);
                ldsm_x4(bl0, bl1, bl2, bl3, addr + TILE_B);
                #pragma unroll
                for (int mt = 0; mt < 2; mt++) {
                    float* e = acc[mt][nb * 2];
                    float* o = acc[mt][nb * 2 + 1];
                    mma_bf16(e[0], e[1], e[2], e[3],
                             ah[mt][0], ah[mt][1], ah[mt][2], ah[mt][3], bh0, bh1);
                    mma_bf16(e[0], e[1], e[2], e[3],
                             ah[mt][0], ah[mt][1], ah[mt][2], ah[mt][3], bl0, bl1);
                    mma_bf16(e[0], e[1], e[2], e[3],
                             al[mt][0], al[mt][1], al[mt][2], al[mt][3], bh0, bh1);
                    mma_bf16(o[0], o[1], o[2], o[3],
                             ah[mt][0], ah[mt][1], ah[mt][2], ah[mt][3], bh2, bh3);
                    mma_bf16(o[0], o[1], o[2], o[3],
                             ah[mt][0], ah[mt][1], ah[mt][2], ah[mt][3], bl2, bl3);
                    mma_bf16(o[0], o[1], o[2], o[3],
                             al[mt][0], al[mt][1], al[mt][2], al[mt][3], bh2, bh3);
                }
            }
        }
        if (kc + 1 < NC) CP_WAIT0();
        __syncthreads();
    }

    // epilogue
    #pragma unroll
    for (int mt = 0; mt < 2; mt++) {
        #pragma unroll
        for (int nt = 0; nt < 8; nt++) {
            int col = n0 + warp_n * 64 + nt * 8 + (lane & 3) * 2;
            #pragma unroll
            for (int half = 0; half < 2; half++) {
                int row = m0 + warp_m * 32 + mt * 16 + (lane >> 2) + half * 8;
                float v0 = acc[mt][nt][half * 2 + 0] + bias[col + 0];
                float v1 = acc[mt][nt][half * 2 + 1] + bias[col + 1];
                if (outF) {
                    if (R) {
                        const float2 rv = *(const float2*)(R + (size_t)row * N + col);
                        v0 += rv.x; v1 += rv.y;
                    }
                    float2 o2; o2.x = v0; o2.y = v1;
                    *(float2*)(outF + (size_t)row * N + col) = o2;
                } else {
                    if (act) { v0 = gelu_exact(v0); v1 = gelu_exact(v1); }
                    __nv_bfloat16 h0, h1, l0, l1;
                    split_bf16(v0, h0, l0);
                    split_bf16(v1, h1, l1);
                    __nv_bfloat162 hh; hh.x = h0; hh.y = h1;
                    __nv_bfloat162 ll; ll.x = l0; ll.y = l1;
                    *(__nv_bfloat162*)(outH + (size_t)row * N + col) = hh;
                    *(__nv_bfloat162*)(outL + (size_t)row * N + col) = ll;
                }
            }
        }
    }
}

// ================= fused causal flash attention (f32) -> bf16 hi/lo =========
#define AS 68
#define ATTN_SMEM (4 * 64 * AS * 4)

__global__ __launch_bounds__(256) void attn_kernel(const float* __restrict__ q,
                                                   const float* __restrict__ k,
                                                   const float* __restrict__ v,
                                                   __nv_bfloat16* __restrict__ oh,
                                                   __nv_bfloat16* __restrict__ ol) {
    extern __shared__ float smf[];
    float* Qs = smf;
    float* Ks = Qs + 64 * AS;
    float* Vs = Ks + 64 * AS;
    float* Ss = Vs + 64 * AS;

    int qt = blockIdx.x, bh = blockIdx.y;
    int b = bh >> 4, h = bh & 15;
    int q0 = qt * 64;
    int tid = threadIdx.x;
    int wx = tid & 15, wy = tid >> 4;

    size_t base = ((size_t)b * TSEQ) * CDIM + (size_t)h * HDIM;

    #pragma unroll
    for (int i = 0; i < 16; i++) {
        int idx = i * 256 + tid;
        int r = idx >> 6, c = idx & 63;
        Qs[r * AS + c] = q[base + (size_t)(q0 + r) * CDIM + c];
    }

    float mrun[4], lrun[4], acc[4][4];
    #pragma unroll
    for (int i = 0; i < 4; i++) {
        mrun[i] = -1e30f; lrun[i] = 0.f;
        #pragma unroll
        for (int j = 0; j < 4; j++) acc[i][j] = 0.f;
    }

    for (int kt = 0; kt <= qt; kt++) {
        int k0 = kt * 64;
        __syncthreads();
        #pragma unroll
        for (int i = 0; i < 16; i++) {
            int idx = i * 256 + tid;
            int r = idx >> 6, c = idx & 63;
            size_t gidx = base + (size_t)(k0 + r) * CDIM + c;
            Ks[r * AS + c] = k[gidx];
            Vs[r * AS + c] = v[gidx];
        }
        __syncthreads();

        float s[4][4];
        #pragma unroll
        for (int i = 0; i < 4; i++)
            #pragma unroll
            for (int j = 0; j < 4; j++) s[i][j] = 0.f;
        #pragma unroll 4
        for (int d = 0; d < 64; d += 4) {
            float4 qv[4], kv[4];
            #pragma unroll
            for (int i = 0; i < 4; i++) qv[i] = *(const float4*)&Qs[(wy * 4 + i) * AS + d];
            #pragma unroll
            for (int j = 0; j < 4; j++) kv[j] = *(const float4*)&Ks[(wx * 4 + j) * AS + d];
            #pragma unroll
            for (int i = 0; i < 4; i++)
                #pragma unroll
                for (int j = 0; j < 4; j++)
                    s[i][j] += qv[i].x * kv[j].x + qv[i].y * kv[j].y +
                               qv[i].z * kv[j].z + qv[i].w * kv[j].w;
        }
        bool diag = (kt == qt);
        #pragma unroll
        for (int i = 0; i < 4; i++)
            #pragma unroll
            for (int j = 0; j < 4; j++) {
                s[i][j] *= 0.125f;
                if (diag && (wx * 4 + j > wy * 4 + i)) s[i][j] = -1e30f;
            }

        float mt[4], lsum[4];
        #pragma unroll
        for (int i = 0; i < 4; i++)
            mt[i] = fmaxf(fmaxf(s[i][0], s[i][1]), fmaxf(s[i][2], s[i][3]));
        #pragma unroll
        for (int m = 1; m < 16; m <<= 1)
            #pragma unroll
            for (int i = 0; i < 4; i++)
                mt[i] = fmaxf(mt[i], __shfl_xor_sync(0xffffffffu, mt[i], m));
        #pragma unroll
        for (int i = 0; i < 4; i++) {
            float mnew = fmaxf(mrun[i], mt[i]);
            float corr = __expf(mrun[i] - mnew);
            mrun[i] = mnew;
            lsum[i] = 0.f;
            #pragma unroll
            for (int j = 0; j < 4; j++) {
                float p = __expf(s[i][j] - mnew);
                s[i][j] = p;
                lsum[i] += p;
            }
            #pragma unroll
            for (int j = 0; j < 4; j++) acc[i][j] *= corr;
            lrun[i] *= corr;
        }
        #pragma unroll
        for (int m = 1; m < 16; m <<= 1)
            #pragma unroll
            for (int i = 0; i < 4; i++)
                lsum[i] += __shfl_xor_sync(0xffffffffu, lsum[i], m);
        #pragma unroll
        for (int i = 0; i < 4; i++) lrun[i] += lsum[i];

        #pragma unroll
        for (int i = 0; i < 4; i++)
            *(float4*)&Ss[(wy * 4 + i) * AS + wx * 4] =
                make_float4(s[i][0], s[i][1], s[i][2], s[i][3]);
        __syncthreads();

        #pragma unroll 4
        for (int j0 = 0; j0 < 64; j0 += 4) {
            float4 pv[4], vv[4];
            #pragma unroll
            for (int i = 0; i < 4; i++) pv[i] = *(const float4*)&Ss[(wy * 4 + i) * AS + j0];
            #pragma unroll
            for (int jj = 0; jj < 4; jj++) vv[jj] = *(const float4*)&Vs[(j0 + jj) * AS + wx * 4];
            #pragma unroll
            for (int i = 0; i < 4; i++) {
                acc[i][0] += pv[i].x * vv[0].x + pv[i].y * vv[1].x + pv[i].z * vv[2].x + pv[i].w * vv[3].x;
                acc[i][1] += pv[i].x * vv[0].y + pv[i].y * vv[1].y + pv[i].z * vv[2].y + pv[i].w * vv[3].y;
                acc[i][2] += pv[i].x * vv[0].z + pv[i].y * vv[1].z + pv[i].z * vv[2].z + pv[i].w * vv[3].z;
                acc[i][3] += pv[i].x * vv[0].w + pv[i].y * vv[1].w + pv[i].z * vv[2].w + pv[i].w * vv[3].w;
            }
        }
    }

    #pragma unroll
    for (int i = 0; i < 4; i++) {
        float invl = 1.0f / lrun[i];
        float v0 = acc[i][0] * invl, v1 = acc[i][1] * invl;
        float v2 = acc[i][2] * invl, v3 = acc[i][3] * invl;
        __nv_bfloat16 h0, h1, h2, h3, l0, l1, l2, l3;
        split_bf16(v0, h0, l0); split_bf16(v1, h1, l1);
        split_bf16(v2, h2, l2); split_bf16(v3, h3, l3);
        size_t off = base + (size_t)(q0 + wy * 4 + i) * CDIM + wx * 4;
        __nv_bfloat162 hh0; hh0.x = h0; hh0.y = h1;
        __nv_bfloat162 hh1; hh1.x = h2; hh1.y = h3;
        __nv_bfloat162 ll0; ll0.x = l0; ll0.y = l1;
        __nv_bfloat162 ll1; ll1.x = l2; ll1.y = l3;
        ((__nv_bfloat162*)(oh + off))[0] = hh0;
        ((__nv_bfloat162*)(oh + off))[1] = hh1;
        ((__nv_bfloat162*)(ol + off))[0] = ll0;
        ((__nv_bfloat162*)(ol + off))[1] = ll1;
    }
}

// ================= launch ====================================================
extern "C" void kernel_launch(void* const* d_in, const int* in_sizes, int n_in,
                              void* d_out, int out_size) {
    const float* x   = (const float*)d_in[0];
    const float* Wq  = (const float*)d_in[1];
    const float* bq  = (const float*)d_in[2];
    const float* Wk  = (const float*)d_in[3];
    const float* bk  = (const float*)d_in[4];
    const float* Wv  = (const float*)d_in[5];
    const float* bv  = (const float*)d_in[6];
    const float* Wp  = (const float*)d_in[7];
    const float* bp  = (const float*)d_in[8];
    const float* W1  = (const float*)d_in[9];
    const float* b1  = (const float*)d_in[10];
    const float* W2  = (const float*)d_in[11];
    const float* b2  = (const float*)d_in[12];
    const float* g1  = (const float*)d_in[13];
    const float* be1 = (const float*)d_in[14];
    const float* g2  = (const float*)d_in[15];
    const float* be2 = (const float*)d_in[16];
    float* out = (float*)d_out;

    unsigned char* S;
    cudaGetSymbolAddress((void**)&S, g_scratch);
    float* qb  = (float*)(S + OFF_Q);
    float* kb  = (float*)(S + OFF_K);
    float* vb  = (float*)(S + OFF_V);
    float* yb  = (float*)(S + OFF_Y);
    __nv_bfloat16* ln1h = (__nv_bfloat16*)(S + OFF_LN1H);
    __nv_bfloat16* ln1l = (__nv_bfloat16*)(S + OFF_LN1L);
    __nv_bfloat16* atth = (__nv_bfloat16*)(S + OFF_ATTH);
    __nv_bfloat16* attl = (__nv_bfloat16*)(S + OFF_ATTL);
    __nv_bfloat16* ln2h = (__nv_bfloat16*)(S + OFF_LN2H);
    __nv_bfloat16* ln2l = (__nv_bfloat16*)(S + OFF_LN2L);
    __nv_bfloat16* ffh  = (__nv_bfloat16*)(S + OFF_FFH);
    __nv_bfloat16* ffl  = (__nv_bfloat16*)(S + OFF_FFL);
    __nv_bfloat16* wqh = (__nv_bfloat16*)(S + OFF_WQH);
    __nv_bfloat16* wql = (__nv_bfloat16*)(S + OFF_WQL);
    __nv_bfloat16* wkh = (__nv_bfloat16*)(S + OFF_WKH);
    __nv_bfloat16* wkl = (__nv_bfloat16*)(S + OFF_WKL);
    __nv_bfloat16* wvh = (__nv_bfloat16*)(S + OFF_WVH);
    __nv_bfloat16* wvl = (__nv_bfloat16*)(S + OFF_WVL);
    __nv_bfloat16* wph = (__nv_bfloat16*)(S + OFF_WPH);
    __nv_bfloat16* wpl = (__nv_bfloat16*)(S + OFF_WPL);
    __nv_bfloat16* w1h = (__nv_bfloat16*)(S + OFF_W1H);
    __nv_bfloat16* w1l = (__nv_bfloat16*)(S + OFF_W1L);
    __nv_bfloat16* w2h = (__nv_bfloat16*)(S + OFF_W2H);
    __nv_bfloat16* w2l = (__nv_bfloat16*)(S + OFF_W2L);

    cudaFuncSetAttribute(attn_kernel, cudaFuncAttributeMaxDynamicSharedMemorySize, ATTN_SMEM);
    cudaFuncSetAttribute(gemm_tc, cudaFuncAttributeMaxDynamicSharedMemorySize, GEMM_SMEM);

    wconv_kernel<<<dim3(16, 16), 256>>>(Wq, wqh, wql, 1024, 1024);
    wconv_kernel<<<dim3(16, 16), 256>>>(Wk, wkh, wkl, 1024, 1024);
    wconv_kernel<<<dim3(16, 16), 256>>>(Wv, wvh, wvl, 1024, 1024);
    wconv_kernel<<<dim3(16, 16), 256>>>(Wp, wph, wpl, 1024, 1024);
    wconv_kernel<<<dim3(16, 64), 256>>>(W1, w1h, w1l, 1024, 4096);
    wconv_kernel<<<dim3(64, 16), 256>>>(W2, w2h, w2l, 4096, 1024);

    ln_kernel<<<NROWS, 256>>>(x, g1, be1, ln1h, ln1l);

    dim3 gQ(8, 32);     // N=1024
    dim3 gF1(32, 32);   // N=4096
    gemm_tc<<<gQ, 256, GEMM_SMEM>>>(ln1h, ln1l, wqh, wql, bq, nullptr, qb, nullptr, nullptr, 1024, 1024, 0);
    gemm_tc<<<gQ, 256, GEMM_SMEM>>>(ln1h, ln1l, wkh, wkl, bk, nullptr, kb, nullptr, nullptr, 1024, 1024, 0);
    gemm_tc<<<gQ, 256, GEMM_SMEM>>>(ln1h, ln1l, wvh, wvl, bv, nullptr, vb, nullptr, nullptr, 1024, 1024, 0);

    attn_kernel<<<dim3(TSEQ / 64, 4 * NHEADS), 256, ATTN_SMEM>>>(qb, kb, vb, atth, attl);

    gemm_tc<<<gQ, 256, GEMM_SMEM>>>(atth, attl, wph, wpl, bp, x, yb, nullptr, nullptr, 1024, 1024, 0);

    ln_kernel<<<NROWS, 256>>>(yb, g2, be2, ln2h, ln2l);

    gemm_tc<<<gF1, 256, GEMM_SMEM>>>(ln2h, ln2l, w1h, w1l, b1, nullptr, nullptr, ffh, ffl, 1024, 4096, 1);
    gemm_tc<<<gQ, 256, GEMM_SMEM>>>(ffh, ffl, w2h, w2l, b2, yb, out, nullptr, nullptr, 4096, 1024, 0);
}

// round 6
// speedup vs baseline: 2.1609x; 1.2848x over previous
#include <cuda_runtime.h>
#include <cuda_bf16.h>
#include <cstdint>
#include <math.h>

#define NROWS 4096      // B*T
#define CDIM  1024
#define HDIM  64
#define NHEADS 16
#define TSEQ  1024
#define FFDIM 4096

// ================= helpers ==================================================
__device__ __forceinline__ uint32_t smem_to_u32(const void* p) {
    uint32_t a;
    asm("{ .reg .u64 t; cvta.to.shared.u64 t, %1; cvt.u32.u64 %0, t; }"
        : "=r"(a) : "l"(p));
    return a;
}
__device__ __forceinline__ void ldsm_x4(uint32_t& r0, uint32_t& r1,
                                        uint32_t& r2, uint32_t& r3, uint32_t a) {
    asm volatile("ldmatrix.sync.aligned.m8n8.x4.shared.b16 {%0,%1,%2,%3}, [%4];"
                 : "=r"(r0), "=r"(r1), "=r"(r2), "=r"(r3) : "r"(a));
}
__device__ __forceinline__ void ldsm_x4_trans(uint32_t& r0, uint32_t& r1,
                                              uint32_t& r2, uint32_t& r3, uint32_t a) {
    asm volatile("ldmatrix.sync.aligned.m8n8.x4.trans.shared.b16 {%0,%1,%2,%3}, [%4];"
                 : "=r"(r0), "=r"(r1), "=r"(r2), "=r"(r3) : "r"(a));
}
__device__ __forceinline__ void mma_bf16(float* d,
                                         uint32_t a0, uint32_t a1, uint32_t a2, uint32_t a3,
                                         uint32_t b0, uint32_t b1) {
    asm volatile("mma.sync.aligned.m16n8k16.row.col.f32.bf16.bf16.f32 "
                 "{%0,%1,%2,%3}, {%4,%5,%6,%7}, {%8,%9}, {%0,%1,%2,%3};"
                 : "+f"(d[0]), "+f"(d[1]), "+f"(d[2]), "+f"(d[3])
                 : "r"(a0), "r"(a1), "r"(a2), "r"(a3), "r"(b0), "r"(b1));
}
#define CP_ASYNC16(dst, src) \
    asm volatile("cp.async.cg.shared.global [%0], [%1], 16;" :: "r"(dst), "l"(src))
#define CP_COMMIT() asm volatile("cp.async.commit_group;" ::: "memory")
#define CP_WAIT0()  asm volatile("cp.async.wait_group 0;" ::: "memory")

__device__ __forceinline__ void split_bf16(float v, __nv_bfloat16& h, __nv_bfloat16& l) {
    h = __float2bfloat16(v);
    l = __float2bfloat16(v - __bfloat162float(h));
}
__device__ __forceinline__ uint32_t packh(__nv_bfloat16 a, __nv_bfloat16 b) {
    __nv_bfloat162 t; t.x = a; t.y = b;
    return *(uint32_t*)&t;
}
// pack P element pair into bf16x2 hi + lo residual (v0 -> low half)
__device__ __forceinline__ void splitpack(float v0, float v1, uint32_t& ph, uint32_t& pl) {
    __nv_bfloat16 h0 = __float2bfloat16(v0), h1 = __float2bfloat16(v1);
    ph = packh(h0, h1);
    float l0 = v0 - __bfloat162float(h0), l1 = v1 - __bfloat162float(h1);
    asm("cvt.rn.bf16x2.f32 %0, %1, %2;" : "=r"(pl) : "f"(l1), "f"(l0));
}
__device__ __forceinline__ float gelu_exact(float v) {
    return 0.5f * v * (1.0f + erff(v * 0.70710678118654752f));
}

// ================= scratch ==================================================
#define MB (1024ull * 1024ull)
__device__ __align__(1024) unsigned char g_scratch[224 * MB];
#define OFF_QH    (0 * MB)
#define OFF_QL    (8 * MB)
#define OFF_KH    (16 * MB)
#define OFF_KL    (24 * MB)
#define OFF_VH    (32 * MB)
#define OFF_VL    (40 * MB)
#define OFF_Y     (48 * MB)
#define OFF_LN1H  (64 * MB)
#define OFF_LN1L  (72 * MB)
#define OFF_ATTH  (80 * MB)
#define OFF_ATTL  (88 * MB)
#define OFF_LN2H  (96 * MB)
#define OFF_LN2L  (104 * MB)
#define OFF_FFH   (112 * MB)
#define OFF_FFL   (144 * MB)
#define OFF_WQH   (176 * MB)
#define OFF_WQL   (178 * MB)
#define OFF_WKH   (180 * MB)
#define OFF_WKL   (182 * MB)
#define OFF_WVH   (184 * MB)
#define OFF_WVL   (186 * MB)
#define OFF_WPH   (188 * MB)
#define OFF_WPL   (190 * MB)
#define OFF_W1H   (192 * MB)
#define OFF_W1L   (200 * MB)
#define OFF_W2H   (208 * MB)
#define OFF_W2L   (216 * MB)

// ================= weight convert+transpose: W[K,N]f32 -> Wh/Wl[N,K]bf16 ====
__global__ __launch_bounds__(256) void wconv_kernel(const float* __restrict__ W,
                                                    __nv_bfloat16* __restrict__ Wh,
                                                    __nv_bfloat16* __restrict__ Wl,
                                                    int K, int N) {
    __shared__ float t[64][65];
    int k0 = blockIdx.x * 64, n0 = blockIdx.y * 64;
    int tid = threadIdx.x;
    #pragma unroll
    for (int i = 0; i < 16; i++) {
        int idx = i * 256 + tid;
        int r = idx >> 6, c = idx & 63;
        t[r][c] = W[(size_t)(k0 + r) * N + n0 + c];
    }
    __syncthreads();
    #pragma unroll
    for (int i = 0; i < 16; i++) {
        int idx = i * 256 + tid;
        int r = idx >> 6, c = idx & 63;
        float v = t[c][r];
        __nv_bfloat16 h, l;
        split_bf16(v, h, l);
        size_t o = (size_t)(n0 + r) * K + k0 + c;
        Wh[o] = h; Wl[o] = l;
    }
}

// ================= layernorm -> bf16 hi/lo ==================================
__global__ __launch_bounds__(256) void ln_kernel(const float* __restrict__ x,
                                                 const float* __restrict__ g,
                                                 const float* __restrict__ b,
                                                 __nv_bfloat16* __restrict__ H,
                                                 __nv_bfloat16* __restrict__ L) {
    int row = blockIdx.x;
    int t = threadIdx.x;
    const float4* xr = (const float4*)(x + (size_t)row * CDIM);
    float4 xv = xr[t];
    float s  = xv.x + xv.y + xv.z + xv.w;
    float ss = xv.x * xv.x + xv.y * xv.y + xv.z * xv.z + xv.w * xv.w;
    #pragma unroll
    for (int m = 16; m; m >>= 1) {
        s  += __shfl_xor_sync(0xffffffffu, s,  m);
        ss += __shfl_xor_sync(0xffffffffu, ss, m);
    }
    __shared__ float rs[8], rss[8];
    int warp = t >> 5, lane = t & 31;
    if (lane == 0) { rs[warp] = s; rss[warp] = ss; }
    __syncthreads();
    float tot = 0.f, tots = 0.f;
    #pragma unroll
    for (int i = 0; i < 8; i++) { tot += rs[i]; tots += rss[i]; }
    float mu  = tot * (1.0f / CDIM);
    float var = tots * (1.0f / CDIM) - mu * mu;
    float inv = rsqrtf(var + 1e-5f);
    float4 gv = ((const float4*)g)[t];
    float4 bv = ((const float4*)b)[t];
    float o0 = (xv.x - mu) * inv * gv.x + bv.x;
    float o1 = (xv.y - mu) * inv * gv.y + bv.y;
    float o2 = (xv.z - mu) * inv * gv.z + bv.z;
    float o3 = (xv.w - mu) * inv * gv.w + bv.w;
    __nv_bfloat16 h0, h1, h2, h3, l0, l1, l2, l3;
    split_bf16(o0, h0, l0); split_bf16(o1, h1, l1);
    split_bf16(o2, h2, l2); split_bf16(o3, h3, l3);
    __nv_bfloat162* Hp = (__nv_bfloat162*)(H + (size_t)row * CDIM + t * 4);
    __nv_bfloat162* Lp = (__nv_bfloat162*)(L + (size_t)row * CDIM + t * 4);
    __nv_bfloat162 a01; a01.x = h0; a01.y = h1;
    __nv_bfloat162 a23; a23.x = h2; a23.y = h3;
    __nv_bfloat162 b01; b01.x = l0; b01.y = l1;
    __nv_bfloat162 b23; b23.x = l2; b23.y = l3;
    Hp[0] = a01; Hp[1] = a23;
    Lp[0] = b01; Lp[1] = b23;
}

// ================= HMMA bf16x3 GEMM =========================================
#define TSTR 80
#define TILE_B (128 * TSTR)
#define BUF_B  (4 * TILE_B)
#define GEMM_SMEM (2 * BUF_B)

__global__ __launch_bounds__(256) void gemm_tc(
    const __nv_bfloat16* __restrict__ Ah, const __nv_bfloat16* __restrict__ Al,
    const __nv_bfloat16* __restrict__ Bh, const __nv_bfloat16* __restrict__ Bl,
    const float* __restrict__ bias, const float* __restrict__ R,
    float* __restrict__ outF, __nv_bfloat16* __restrict__ outH,
    __nv_bfloat16* __restrict__ outL, int K, int N, int act) {
    extern __shared__ char sm[];
    uint32_t sbase = smem_to_u32(sm);
    int tid = threadIdx.x;
    int wid = tid >> 5, lane = tid & 31;
    int warp_m = wid & 3, warp_n = wid >> 2;
    int n0 = blockIdx.x * 128;
    int m0 = blockIdx.y * 128;
    int NC = K >> 5;

    float acc[2][8][4];
    #pragma unroll
    for (int i = 0; i < 2; i++)
        #pragma unroll
        for (int j = 0; j < 8; j++)
            #pragma unroll
            for (int c = 0; c < 4; c++) acc[i][j][c] = 0.f;

    const __nv_bfloat16* tiles[4] = {Ah, Al, Bh, Bl};
    int row0s[4] = {m0, m0, n0, n0};
    int ldr = tid >> 2;
    int ldc = tid & 3;

    #pragma unroll
    for (int t = 0; t < 4; t++)
        #pragma unroll
        for (int it = 0; it < 2; it++) {
            int r = it * 64 + ldr;
            uint32_t dst = sbase + t * TILE_B + r * TSTR + ldc * 16;
            const __nv_bfloat16* src = tiles[t] + (size_t)(row0s[t] + r) * K + ldc * 8;
            CP_ASYNC16(dst, src);
        }
    CP_COMMIT();
    CP_WAIT0();
    __syncthreads();

    int a_row = (lane & 7) + ((lane >> 3) & 1) * 8;
    int a_kb  = ((lane >> 4) & 1) * 16;
    int b_row = (lane & 7) + ((lane >> 4) & 1) * 8;
    int b_kb  = ((lane >> 3) & 1) * 16;

    for (int kc = 0; kc < NC; kc++) {
        int b = kc & 1;
        uint32_t sbuf = sbase + b * BUF_B;
        if (kc + 1 < NC) {
            uint32_t dbuf = sbase + (b ^ 1) * BUF_B;
            int k0 = (kc + 1) * 32;
            #pragma unroll
            for (int t = 0; t < 4; t++)
                #pragma unroll
                for (int it = 0; it < 2; it++) {
                    int r = it * 64 + ldr;
                    uint32_t dst = dbuf + t * TILE_B + r * TSTR + ldc * 16;
                    const __nv_bfloat16* src = tiles[t] + (size_t)(row0s[t] + r) * K + k0 + ldc * 8;
                    CP_ASYNC16(dst, src);
                }
            CP_COMMIT();
        }

        #pragma unroll
        for (int ks = 0; ks < 2; ks++) {
            int kb = ks * 32;
            uint32_t ah[2][4], al[2][4];
            #pragma unroll
            for (int mt = 0; mt < 2; mt++) {
                uint32_t addr = sbuf + (warp_m * 32 + mt * 16 + a_row) * TSTR + kb + a_kb;
                ldsm_x4(ah[mt][0], ah[mt][1], ah[mt][2], ah[mt][3], addr);
                ldsm_x4(al[mt][0], al[mt][1], al[mt][2], al[mt][3], addr + TILE_B);
            }
            #pragma unroll
            for (int nb = 0; nb < 4; nb++) {
                uint32_t addr = sbuf + 2 * TILE_B +
                                (warp_n * 64 + nb * 16 + b_row) * TSTR + kb + b_kb;
                uint32_t bh0, bh1, bh2, bh3, bl0, bl1, bl2, bl3;
                ldsm_x4(bh0, bh1, bh2, bh3, addr);
                ldsm_x4(bl0, bl1, bl2, bl3, addr + TILE_B);
                #pragma unroll
                for (int mt = 0; mt < 2; mt++) {
                    float* e = acc[mt][nb * 2];
                    float* o = acc[mt][nb * 2 + 1];
                    mma_bf16(e, ah[mt][0], ah[mt][1], ah[mt][2], ah[mt][3], bh0, bh1);
                    mma_bf16(e, ah[mt][0], ah[mt][1], ah[mt][2], ah[mt][3], bl0, bl1);
                    mma_bf16(e, al[mt][0], al[mt][1], al[mt][2], al[mt][3], bh0, bh1);
                    mma_bf16(o, ah[mt][0], ah[mt][1], ah[mt][2], ah[mt][3], bh2, bh3);
                    mma_bf16(o, ah[mt][0], ah[mt][1], ah[mt][2], ah[mt][3], bl2, bl3);
                    mma_bf16(o, al[mt][0], al[mt][1], al[mt][2], al[mt][3], bh2, bh3);
                }
            }
        }
        if (kc + 1 < NC) CP_WAIT0();
        __syncthreads();
    }

    #pragma unroll
    for (int mt = 0; mt < 2; mt++) {
        #pragma unroll
        for (int nt = 0; nt < 8; nt++) {
            int col = n0 + warp_n * 64 + nt * 8 + (lane & 3) * 2;
            #pragma unroll
            for (int half = 0; half < 2; half++) {
                int row = m0 + warp_m * 32 + mt * 16 + (lane >> 2) + half * 8;
                float v0 = acc[mt][nt][half * 2 + 0] + bias[col + 0];
                float v1 = acc[mt][nt][half * 2 + 1] + bias[col + 1];
                if (outF) {
                    if (R) {
                        const float2 rv = *(const float2*)(R + (size_t)row * N + col);
                        v0 += rv.x; v1 += rv.y;
                    }
                    float2 o2; o2.x = v0; o2.y = v1;
                    *(float2*)(outF + (size_t)row * N + col) = o2;
                } else {
                    if (act) { v0 = gelu_exact(v0); v1 = gelu_exact(v1); }
                    __nv_bfloat16 h0, h1, l0, l1;
                    split_bf16(v0, h0, l0);
                    split_bf16(v1, h1, l1);
                    __nv_bfloat162 hh; hh.x = h0; hh.y = h1;
                    __nv_bfloat162 ll; ll.x = l0; ll.y = l1;
                    *(__nv_bfloat162*)(outH + (size_t)row * N + col) = hh;
                    *(__nv_bfloat162*)(outL + (size_t)row * N + col) = ll;
                }
            }
        }
    }
}

// ================= HMMA flash attention =====================================
// 256 threads (8 warps), q-tile 128 (16 rows/warp), key tiles of 64.
// Q,K,V bf16 hi/lo; S and O error-compensated (3-term MMA).
#define ATS 144
#define ATTN_SMEM (2 * 128 * ATS + 4 * 64 * ATS)   // 36864 + 36864 = 73728

__global__ __launch_bounds__(256) void attn_tc(
    const __nv_bfloat16* __restrict__ qh, const __nv_bfloat16* __restrict__ ql,
    const __nv_bfloat16* __restrict__ kh, const __nv_bfloat16* __restrict__ kl,
    const __nv_bfloat16* __restrict__ vh, const __nv_bfloat16* __restrict__ vl,
    __nv_bfloat16* __restrict__ oh, __nv_bfloat16* __restrict__ ol) {
    extern __shared__ char sm[];
    uint32_t sb = smem_to_u32(sm);
    uint32_t sQh = sb;
    uint32_t sQl = sb + 128 * ATS;
    uint32_t sKh = sb + 2 * 128 * ATS;
    uint32_t sKl = sKh + 64 * ATS;
    uint32_t sVh = sKl + 64 * ATS;
    uint32_t sVl = sVh + 64 * ATS;

    int qb = blockIdx.x, bh = blockIdx.y;
    int b = bh >> 4, h = bh & 15;
    int q0 = qb * 128;
    int tid = threadIdx.x, wid = tid >> 5, lane = tid & 31;
    int g = lane >> 2, t4 = lane & 3;

    size_t base = ((size_t)b * TSEQ) * CDIM + (size_t)h * HDIM;

    // stage Q hi/lo (128 x 64)
    #pragma unroll
    for (int i = 0; i < 4; i++) {
        int idx = i * 256 + tid;
        int r = idx >> 3, c = idx & 7;
        size_t gsrc = base + (size_t)(q0 + r) * CDIM + c * 8;
        CP_ASYNC16(sQh + r * ATS + c * 16, qh + gsrc);
        CP_ASYNC16(sQl + r * ATS + c * 16, ql + gsrc);
    }
    CP_COMMIT();
    CP_WAIT0();
    __syncthreads();

    int a_row = (lane & 7) + ((lane >> 3) & 1) * 8;
    int a_kb  = ((lane >> 4) & 1) * 16;
    int b_row = (lane & 7) + ((lane >> 4) & 1) * 8;
    int b_kb  = ((lane >> 3) & 1) * 16;
    int v_row = (lane & 7) + ((lane >> 3) & 1) * 8;
    int v_cb  = ((lane >> 4) & 1) * 16;

    uint32_t qfh[4][4], qfl[4][4];
    #pragma unroll
    for (int ks = 0; ks < 4; ks++) {
        uint32_t ad = sQh + (wid * 16 + a_row) * ATS + ks * 32 + a_kb;
        ldsm_x4(qfh[ks][0], qfh[ks][1], qfh[ks][2], qfh[ks][3], ad);
        ldsm_x4(qfl[ks][0], qfl[ks][1], qfl[ks][2], qfl[ks][3], ad + 128 * ATS);
    }

    float oacc[8][4];
    #pragma unroll
    for (int i = 0; i < 8; i++)
        #pragma unroll
        for (int c = 0; c < 4; c++) oacc[i][c] = 0.f;
    float mrun0 = -1e30f, mrun1 = -1e30f, lrun0 = 0.f, lrun1 = 0.f;

    int nkt = 2 * qb + 2;
    for (int kt = 0; kt < nkt; kt++) {
        __syncthreads();
        #pragma unroll
        for (int i = 0; i < 2; i++) {
            int idx = i * 256 + tid;
            int r = idx >> 3, c = idx & 7;
            size_t gsrc = base + (size_t)(kt * 64 + r) * CDIM + c * 8;
            uint32_t so = r * ATS + c * 16;
            CP_ASYNC16(sKh + so, kh + gsrc);
            CP_ASYNC16(sKl + so, kl + gsrc);
            CP_ASYNC16(sVh + so, vh + gsrc);
            CP_ASYNC16(sVl + so, vl + gsrc);
        }
        CP_COMMIT();
        CP_WAIT0();
        __syncthreads();

        // S = Q K^T (bf16x3)
        float sacc[8][4];
        #pragma unroll
        for (int i = 0; i < 8; i++)
            #pragma unroll
            for (int c = 0; c < 4; c++) sacc[i][c] = 0.f;

        #pragma unroll
        for (int kg = 0; kg < 4; kg++) {
            #pragma unroll
            for (int ks = 0; ks < 4; ks++) {
                uint32_t ad = sKh + (kg * 16 + b_row) * ATS + ks * 32 + b_kb;
                uint32_t kh0, kh1, kh2, kh3, kl0, kl1, kl2, kl3;
                ldsm_x4(kh0, kh1, kh2, kh3, ad);
                ldsm_x4(kl0, kl1, kl2, kl3, ad + 64 * ATS);
                float* e = sacc[kg * 2];
                float* o = sacc[kg * 2 + 1];
                mma_bf16(e, qfh[ks][0], qfh[ks][1], qfh[ks][2], qfh[ks][3], kh0, kh1);
                mma_bf16(e, qfh[ks][0], qfh[ks][1], qfh[ks][2], qfh[ks][3], kl0, kl1);
                mma_bf16(e, qfl[ks][0], qfl[ks][1], qfl[ks][2], qfl[ks][3], kh0, kh1);
                mma_bf16(o, qfh[ks][0], qfh[ks][1], qfh[ks][2], qfh[ks][3], kh2, kh3);
                mma_bf16(o, qfh[ks][0], qfh[ks][1], qfh[ks][2], qfh[ks][3], kl2, kl3);
                mma_bf16(o, qfl[ks][0], qfl[ks][1], qfl[ks][2], qfl[ks][3], kh2, kh3);
            }
        }

        // scale + causal mask
        int r0g = q0 + wid * 16 + g;
        int r1g = r0g + 8;
        bool maskt = (kt >= 2 * qb);
        #pragma unroll
        for (int nt = 0; nt < 8; nt++) {
            #pragma unroll
            for (int c = 0; c < 4; c++) sacc[nt][c] *= 0.125f;
            if (maskt) {
                int cb = kt * 64 + nt * 8 + 2 * t4;
                if (cb     > r0g) sacc[nt][0] = -1e30f;
                if (cb + 1 > r0g) sacc[nt][1] = -1e30f;
                if (cb     > r1g) sacc[nt][2] = -1e30f;
                if (cb + 1 > r1g) sacc[nt][3] = -1e30f;
            }
        }

        // online softmax
        float mt0 = -1e30f, mt1 = -1e30f;
        #pragma unroll
        for (int nt = 0; nt < 8; nt++) {
            mt0 = fmaxf(mt0, fmaxf(sacc[nt][0], sacc[nt][1]));
            mt1 = fmaxf(mt1, fmaxf(sacc[nt][2], sacc[nt][3]));
        }
        mt0 = fmaxf(mt0, __shfl_xor_sync(0xffffffffu, mt0, 1));
        mt0 = fmaxf(mt0, __shfl_xor_sync(0xffffffffu, mt0, 2));
        mt1 = fmaxf(mt1, __shfl_xor_sync(0xffffffffu, mt1, 1));
        mt1 = fmaxf(mt1, __shfl_xor_sync(0xffffffffu, mt1, 2));

        float mn0 = fmaxf(mrun0, mt0), mn1 = fmaxf(mrun1, mt1);
        float cr0 = __expf(mrun0 - mn0), cr1 = __expf(mrun1 - mn1);
        mrun0 = mn0; mrun1 = mn1;
        #pragma unroll
        for (int nt = 0; nt < 8; nt++) {
            oacc[nt][0] *= cr0; oacc[nt][1] *= cr0;
            oacc[nt][2] *= cr1; oacc[nt][3] *= cr1;
        }
        lrun0 *= cr0; lrun1 *= cr1;

        float ls0 = 0.f, ls1 = 0.f;
        #pragma unroll
        for (int nt = 0; nt < 8; nt++) {
            sacc[nt][0] = __expf(sacc[nt][0] - mn0);
            sacc[nt][1] = __expf(sacc[nt][1] - mn0);
            sacc[nt][2] = __expf(sacc[nt][2] - mn1);
            sacc[nt][3] = __expf(sacc[nt][3] - mn1);
            ls0 += sacc[nt][0] + sacc[nt][1];
            ls1 += sacc[nt][2] + sacc[nt][3];
        }
        ls0 += __shfl_xor_sync(0xffffffffu, ls0, 1);
        ls0 += __shfl_xor_sync(0xffffffffu, ls0, 2);
        ls1 += __shfl_xor_sync(0xffffffffu, ls1, 1);
        ls1 += __shfl_xor_sync(0xffffffffu, ls1, 2);
        lrun0 += ls0; lrun1 += ls1;

        // O += P V (P hi/lo x V hi/lo, 3-term)
        #pragma unroll
        for (int s = 0; s < 4; s++) {
            uint32_t aPh[4], aPl[4];
            splitpack(sacc[2 * s][0],     sacc[2 * s][1],     aPh[0], aPl[0]);
            splitpack(sacc[2 * s][2],     sacc[2 * s][3],     aPh[1], aPl[1]);
            splitpack(sacc[2 * s + 1][0], sacc[2 * s + 1][1], aPh[2], aPl[2]);
            splitpack(sacc[2 * s + 1][2], sacc[2 * s + 1][3], aPh[3], aPl[3]);
            #pragma unroll
            for (int p = 0; p < 4; p++) {
                uint32_t ad = sVh + (s * 16 + v_row) * ATS + p * 32 + v_cb;
                uint32_t vh0, vh1, vh2, vh3, vl0, vl1, vl2, vl3;
                ldsm_x4_trans(vh0, vh1, vh2, vh3, ad);
                ldsm_x4_trans(vl0, vl1, vl2, vl3, ad + 64 * ATS);
                float* e = oacc[p * 2];
                float* o = oacc[p * 2 + 1];
                mma_bf16(e, aPh[0], aPh[1], aPh[2], aPh[3], vh0, vh1);
                mma_bf16(e, aPl[0], aPl[1], aPl[2], aPl[3], vh0, vh1);
                mma_bf16(e, aPh[0], aPh[1], aPh[2], aPh[3], vl0, vl1);
                mma_bf16(o, aPh[0], aPh[1], aPh[2], aPh[3], vh2, vh3);
                mma_bf16(o, aPl[0], aPl[1], aPl[2], aPl[3], vh2, vh3);
                mma_bf16(o, aPh[0], aPh[1], aPh[2], aPh[3], vl2, vl3);
            }
        }
    }

    // finalize + store bf16 hi/lo
    float il0 = 1.0f / lrun0, il1 = 1.0f / lrun1;
    int r0g = q0 + wid * 16 + g;
    #pragma unroll
    for (int nt = 0; nt < 8; nt++) {
        int col = nt * 8 + 2 * t4;
        float v0 = oacc[nt][0] * il0, v1 = oacc[nt][1] * il0;
        float v2 = oacc[nt][2] * il1, v3 = oacc[nt][3] * il1;
        __nv_bfloat16 h0, h1, h2, h3, l0, l1, l2, l3;
        split_bf16(v0, h0, l0); split_bf16(v1, h1, l1);
        split_bf16(v2, h2, l2); split_bf16(v3, h3, l3);
        size_t o0 = base + (size_t)r0g * CDIM + col;
        size_t o1 = base + (size_t)(r0g + 8) * CDIM + col;
        __nv_bfloat162 t;
        t.x = h0; t.y = h1; *(__nv_bfloat162*)(oh + o0) = t;
        t.x = l0; t.y = l1; *(__nv_bfloat162*)(ol + o0) = t;
        t.x = h2; t.y = h3; *(__nv_bfloat162*)(oh + o1) = t;
        t.x = l2; t.y = l3; *(__nv_bfloat162*)(ol + o1) = t;
    }
}

// ================= launch ====================================================
extern "C" void kernel_launch(void* const* d_in, const int* in_sizes, int n_in,
                              void* d_out, int out_size) {
    const float* x   = (const float*)d_in[0];
    const float* Wq  = (const float*)d_in[1];
    const float* bq  = (const float*)d_in[2];
    const float* Wk  = (const float*)d_in[3];
    const float* bk  = (const float*)d_in[4];
    const float* Wv  = (const float*)d_in[5];
    const float* bv  = (const float*)d_in[6];
    const float* Wp  = (const float*)d_in[7];
    const float* bp  = (const float*)d_in[8];
    const float* W1  = (const float*)d_in[9];
    const float* b1  = (const float*)d_in[10];
    const float* W2  = (const float*)d_in[11];
    const float* b2  = (const float*)d_in[12];
    const float* g1  = (const float*)d_in[13];
    const float* be1 = (const float*)d_in[14];
    const float* g2  = (const float*)d_in[15];
    const float* be2 = (const float*)d_in[16];
    float* out = (float*)d_out;

    unsigned char* S;
    cudaGetSymbolAddress((void**)&S, g_scratch);
    __nv_bfloat16* qhB = (__nv_bfloat16*)(S + OFF_QH);
    __nv_bfloat16* qlB = (__nv_bfloat16*)(S + OFF_QL);
    __nv_bfloat16* khB = (__nv_bfloat16*)(S + OFF_KH);
    __nv_bfloat16* klB = (__nv_bfloat16*)(S + OFF_KL);
    __nv_bfloat16* vhB = (__nv_bfloat16*)(S + OFF_VH);
    __nv_bfloat16* vlB = (__nv_bfloat16*)(S + OFF_VL);
    float* yb  = (float*)(S + OFF_Y);
    __nv_bfloat16* ln1h = (__nv_bfloat16*)(S + OFF_LN1H);
    __nv_bfloat16* ln1l = (__nv_bfloat16*)(S + OFF_LN1L);
    __nv_bfloat16* atth = (__nv_bfloat16*)(S + OFF_ATTH);
    __nv_bfloat16* attl = (__nv_bfloat16*)(S + OFF_ATTL);
    __nv_bfloat16* ln2h = (__nv_bfloat16*)(S + OFF_LN2H);
    __nv_bfloat16* ln2l = (__nv_bfloat16*)(S + OFF_LN2L);
    __nv_bfloat16* ffh  = (__nv_bfloat16*)(S + OFF_FFH);
    __nv_bfloat16* ffl  = (__nv_bfloat16*)(S + OFF_FFL);
    __nv_bfloat16* wqh = (__nv_bfloat16*)(S + OFF_WQH);
    __nv_bfloat16* wql = (__nv_bfloat16*)(S + OFF_WQL);
    __nv_bfloat16* wkh = (__nv_bfloat16*)(S + OFF_WKH);
    __nv_bfloat16* wkl = (__nv_bfloat16*)(S + OFF_WKL);
    __nv_bfloat16* wvh = (__nv_bfloat16*)(S + OFF_WVH);
    __nv_bfloat16* wvl = (__nv_bfloat16*)(S + OFF_WVL);
    __nv_bfloat16* wph = (__nv_bfloat16*)(S + OFF_WPH);
    __nv_bfloat16* wpl = (__nv_bfloat16*)(S + OFF_WPL);
    __nv_bfloat16* w1h = (__nv_bfloat16*)(S + OFF_W1H);
    __nv_bfloat16* w1l = (__nv_bfloat16*)(S + OFF_W1L);
    __nv_bfloat16* w2h = (__nv_bfloat16*)(S + OFF_W2H);
    __nv_bfloat16* w2l = (__nv_bfloat16*)(S + OFF_W2L);

    cudaFuncSetAttribute(attn_tc, cudaFuncAttributeMaxDynamicSharedMemorySize, ATTN_SMEM);
    cudaFuncSetAttribute(gemm_tc, cudaFuncAttributeMaxDynamicSharedMemorySize, GEMM_SMEM);

    wconv_kernel<<<dim3(16, 16), 256>>>(Wq, wqh, wql, 1024, 1024);
    wconv_kernel<<<dim3(16, 16), 256>>>(Wk, wkh, wkl, 1024, 1024);
    wconv_kernel<<<dim3(16, 16), 256>>>(Wv, wvh, wvl, 1024, 1024);
    wconv_kernel<<<dim3(16, 16), 256>>>(Wp, wph, wpl, 1024, 1024);
    wconv_kernel<<<dim3(16, 64), 256>>>(W1, w1h, w1l, 1024, 4096);
    wconv_kernel<<<dim3(64, 16), 256>>>(W2, w2h, w2l, 4096, 1024);

    ln_kernel<<<NROWS, 256>>>(x, g1, be1, ln1h, ln1l);

    dim3 gQ(8, 32);
    dim3 gF1(32, 32);
    gemm_tc<<<gQ, 256, GEMM_SMEM>>>(ln1h, ln1l, wqh, wql, bq, nullptr, nullptr, qhB, qlB, 1024, 1024, 0);
    gemm_tc<<<gQ, 256, GEMM_SMEM>>>(ln1h, ln1l, wkh, wkl, bk, nullptr, nullptr, khB, klB, 1024, 1024, 0);
    gemm_tc<<<gQ, 256, GEMM_SMEM>>>(ln1h, ln1l, wvh, wvl, bv, nullptr, nullptr, vhB, vlB, 1024, 1024, 0);

    attn_tc<<<dim3(TSEQ / 128, 4 * NHEADS), 256, ATTN_SMEM>>>(qhB, qlB, khB, klB, vhB, vlB, atth, attl);

    gemm_tc<<<gQ, 256, GEMM_SMEM>>>(atth, attl, wph, wpl, bp, x, yb, nullptr, nullptr, 1024, 1024, 0);

    ln_kernel<<<NROWS, 256>>>(yb, g2, be2, ln2h, ln2l);

    gemm_tc<<<gF1, 256, GEMM_SMEM>>>(ln2h, ln2l, w1h, w1l, b1, nullptr, nullptr, ffh, ffl, 1024, 4096, 1);
    gemm_tc<<<gQ, 256, GEMM_SMEM>>>(ffh, ffl, w2h, w2l, b2, yb, out, nullptr, nullptr, 4096, 1024, 0);
}

// round 9
// speedup vs baseline: 2.4828x; 1.1490x over previous
#include <cuda_runtime.h>
#include <cuda_bf16.h>
#include <cstdint>
#include <math.h>

#define NROWS 4096      // B*T
#define CDIM  1024
#define HDIM  64
#define NHEADS 16
#define TSEQ  1024
#define FFDIM 4096

// ================= helpers ==================================================
__device__ __forceinline__ uint32_t smem_to_u32(const void* p) {
    uint32_t a;
    asm("{ .reg .u64 t; cvta.to.shared.u64 t, %1; cvt.u32.u64 %0, t; }"
        : "=r"(a) : "l"(p));
    return a;
}
__device__ __forceinline__ void ldsm_x4(uint32_t& r0, uint32_t& r1,
                                        uint32_t& r2, uint32_t& r3, uint32_t a) {
    asm volatile("ldmatrix.sync.aligned.m8n8.x4.shared.b16 {%0,%1,%2,%3}, [%4];"
                 : "=r"(r0), "=r"(r1), "=r"(r2), "=r"(r3) : "r"(a));
}
__device__ __forceinline__ void ldsm_x4_trans(uint32_t& r0, uint32_t& r1,
                                              uint32_t& r2, uint32_t& r3, uint32_t a) {
    asm volatile("ldmatrix.sync.aligned.m8n8.x4.trans.shared.b16 {%0,%1,%2,%3}, [%4];"
                 : "=r"(r0), "=r"(r1), "=r"(r2), "=r"(r3) : "r"(a));
}
__device__ __forceinline__ void mma_bf16(float* d,
                                         uint32_t a0, uint32_t a1, uint32_t a2, uint32_t a3,
                                         uint32_t b0, uint32_t b1) {
    asm volatile("mma.sync.aligned.m16n8k16.row.col.f32.bf16.bf16.f32 "
                 "{%0,%1,%2,%3}, {%4,%5,%6,%7}, {%8,%9}, {%0,%1,%2,%3};"
                 : "+f"(d[0]), "+f"(d[1]), "+f"(d[2]), "+f"(d[3])
                 : "r"(a0), "r"(a1), "r"(a2), "r"(a3), "r"(b0), "r"(b1));
}
#define CP_ASYNC16(dst, src) \
    asm volatile("cp.async.cg.shared.global [%0], [%1], 16;" :: "r"(dst), "l"(src))
#define CP_COMMIT() asm volatile("cp.async.commit_group;" ::: "memory")
#define CP_WAIT0()  asm volatile("cp.async.wait_group 0;" ::: "memory")

__device__ __forceinline__ void split_bf16(float v, __nv_bfloat16& h, __nv_bfloat16& l) {
    h = __float2bfloat16(v);
    l = __float2bfloat16(v - __bfloat162float(h));
}
__device__ __forceinline__ uint32_t packh(__nv_bfloat16 a, __nv_bfloat16 b) {
    __nv_bfloat162 t; t.x = a; t.y = b;
    return *(uint32_t*)&t;
}
__device__ __forceinline__ void splitpack(float v0, float v1, uint32_t& ph, uint32_t& pl) {
    __nv_bfloat16 h0 = __float2bfloat16(v0), h1 = __float2bfloat16(v1);
    ph = packh(h0, h1);
    float l0 = v0 - __bfloat162float(h0), l1 = v1 - __bfloat162float(h1);
    asm("cvt.rn.bf16x2.f32 %0, %1, %2;" : "=r"(pl) : "f"(l1), "f"(l0));
}
__device__ __forceinline__ float gelu_exact(float v) {
    return 0.5f * v * (1.0f + erff(v * 0.70710678118654752f));
}

// ================= scratch ==================================================
#define MB (1024ull * 1024ull)
__device__ __align__(1024) unsigned char g_scratch[225 * MB];
#define OFF_QH    (0 * MB)
#define OFF_QL    (8 * MB)
#define OFF_KH    (16 * MB)
#define OFF_KL    (24 * MB)
#define OFF_VH    (32 * MB)
#define OFF_VL    (40 * MB)
#define OFF_Y     (48 * MB)
#define OFF_LN1H  (64 * MB)
#define OFF_LN1L  (72 * MB)
#define OFF_ATTH  (80 * MB)
#define OFF_ATTL  (88 * MB)
#define OFF_LN2H  (96 * MB)
#define OFF_LN2L  (104 * MB)
#define OFF_FFH   (112 * MB)
#define OFF_FFL   (144 * MB)
#define OFF_WQKVH (176 * MB)   // [3072,1024] bf16 = 6MB
#define OFF_WQKVL (182 * MB)
#define OFF_WPH   (188 * MB)
#define OFF_WPL   (190 * MB)
#define OFF_W1H   (192 * MB)
#define OFF_W1L   (200 * MB)
#define OFF_W2H   (208 * MB)
#define OFF_W2L   (216 * MB)
#define OFF_BIASC (224 * MB)   // concat qkv bias [3072] f32
#define QKV_SEL_STRIDE 8388608ull   // 16MB / 2B: q->k->v buffer spacing in elements

// ================= bias concat (replaces memcpyAsync) =======================
__global__ __launch_bounds__(1024) void bias_concat_kernel(
    const float* __restrict__ bq, const float* __restrict__ bk,
    const float* __restrict__ bv, float* __restrict__ dst) {
    int i = threadIdx.x;
    const float* src = (blockIdx.x == 0) ? bq : (blockIdx.x == 1) ? bk : bv;
    dst[blockIdx.x * 1024 + i] = src[i];
}

// ================= weight convert+transpose: W[K,N]f32 -> Wh/Wl[N,K]bf16 ====
__global__ __launch_bounds__(256) void wconv_kernel(const float* __restrict__ W,
                                                    __nv_bfloat16* __restrict__ Wh,
                                                    __nv_bfloat16* __restrict__ Wl,
                                                    int K, int N) {
    __shared__ float t[64][65];
    int k0 = blockIdx.x * 64, n0 = blockIdx.y * 64;
    int tid = threadIdx.x;
    #pragma unroll
    for (int i = 0; i < 16; i++) {
        int idx = i * 256 + tid;
        int r = idx >> 6, c = idx & 63;
        t[r][c] = W[(size_t)(k0 + r) * N + n0 + c];
    }
    __syncthreads();
    #pragma unroll
    for (int i = 0; i < 16; i++) {
        int idx = i * 256 + tid;
        int r = idx >> 6, c = idx & 63;
        float v = t[c][r];
        __nv_bfloat16 h, l;
        split_bf16(v, h, l);
        size_t o = (size_t)(n0 + r) * K + k0 + c;
        Wh[o] = h; Wl[o] = l;
    }
}

// ================= layernorm -> bf16 hi/lo ==================================
__global__ __launch_bounds__(256) void ln_kernel(const float* __restrict__ x,
                                                 const float* __restrict__ g,
                                                 const float* __restrict__ b,
                                                 __nv_bfloat16* __restrict__ H,
                                                 __nv_bfloat16* __restrict__ L) {
    int row = blockIdx.x;
    int t = threadIdx.x;
    const float4* xr = (const float4*)(x + (size_t)row * CDIM);
    float4 xv = xr[t];
    float s  = xv.x + xv.y + xv.z + xv.w;
    float ss = xv.x * xv.x + xv.y * xv.y + xv.z * xv.z + xv.w * xv.w;
    #pragma unroll
    for (int m = 16; m; m >>= 1) {
        s  += __shfl_xor_sync(0xffffffffu, s,  m);
        ss += __shfl_xor_sync(0xffffffffu, ss, m);
    }
    __shared__ float rs[8], rss[8];
    int warp = t >> 5, lane = t & 31;
    if (lane == 0) { rs[warp] = s; rss[warp] = ss; }
    __syncthreads();
    float tot = 0.f, tots = 0.f;
    #pragma unroll
    for (int i = 0; i < 8; i++) { tot += rs[i]; tots += rss[i]; }
    float mu  = tot * (1.0f / CDIM);
    float var = tots * (1.0f / CDIM) - mu * mu;
    float inv = rsqrtf(var + 1e-5f);
    float4 gv = ((const float4*)g)[t];
    float4 bv = ((const float4*)b)[t];
    float o0 = (xv.x - mu) * inv * gv.x + bv.x;
    float o1 = (xv.y - mu) * inv * gv.y + bv.y;
    float o2 = (xv.z - mu) * inv * gv.z + bv.z;
    float o3 = (xv.w - mu) * inv * gv.w + bv.w;
    __nv_bfloat16 h0, h1, h2, h3, l0, l1, l2, l3;
    split_bf16(o0, h0, l0); split_bf16(o1, h1, l1);
    split_bf16(o2, h2, l2); split_bf16(o3, h3, l3);
    __nv_bfloat162* Hp = (__nv_bfloat162*)(H + (size_t)row * CDIM + t * 4);
    __nv_bfloat162* Lp = (__nv_bfloat162*)(L + (size_t)row * CDIM + t * 4);
    __nv_bfloat162 a01; a01.x = h0; a01.y = h1;
    __nv_bfloat162 a23; a23.x = h2; a23.y = h3;
    __nv_bfloat162 b01; b01.x = l0; b01.y = l1;
    __nv_bfloat162 b23; b23.x = l2; b23.y = l3;
    Hp[0] = a01; Hp[1] = a23;
    Lp[0] = b01; Lp[1] = b23;
}

// ================= HMMA bf16x3 GEMM =========================================
// qkv mode: blockIdx.x in [0,24): which = bx>>3 selects q/k/v (out += which*
// QKV_SEL_STRIDE, bias concat indexed bx*128), weight rows = bx*128 in the
// [3072,K] concat weight, output col = (bx&7)*128.
#define TSTR 80
#define TILE_B (128 * TSTR)
#define BUF_B  (4 * TILE_B)
#define GEMM_SMEM (2 * BUF_B)

__global__ __launch_bounds__(256, 2) void gemm_tc(
    const __nv_bfloat16* __restrict__ Ah, const __nv_bfloat16* __restrict__ Al,
    const __nv_bfloat16* __restrict__ Bh, const __nv_bfloat16* __restrict__ Bl,
    const float* __restrict__ bias, const float* __restrict__ R,
    float* __restrict__ outF, __nv_bfloat16* __restrict__ outH,
    __nv_bfloat16* __restrict__ outL, int K, int N, int act, int qkv) {
    extern __shared__ char sm[];
    uint32_t sbase = smem_to_u32(sm);
    int tid = threadIdx.x;
    int wid = tid >> 5, lane = tid & 31;
    int warp_m = wid & 3, warp_n = wid >> 2;
    int bx = blockIdx.x;
    int wrow0 = bx * 128;                       // weight rows (concat space)
    int n0 = qkv ? ((bx & 7) * 128) : wrow0;    // output col base
    const float* biasP = bias + (qkv ? bx * 128 : n0);
    size_t osel = qkv ? (size_t)(bx >> 3) * QKV_SEL_STRIDE : 0;
    int m0 = blockIdx.y * 128;
    int NC = K >> 5;

    float acc[2][8][4];
    #pragma unroll
    for (int i = 0; i < 2; i++)
        #pragma unroll
        for (int j = 0; j < 8; j++)
            #pragma unroll
            for (int c = 0; c < 4; c++) acc[i][j][c] = 0.f;

    const __nv_bfloat16* tiles[4] = {Ah, Al, Bh, Bl};
    int row0s[4] = {m0, m0, wrow0, wrow0};
    int ldr = tid >> 2;
    int ldc = tid & 3;

    #pragma unroll
    for (int t = 0; t < 4; t++)
        #pragma unroll
        for (int it = 0; it < 2; it++) {
            int r = it * 64 + ldr;
            uint32_t dst = sbase + t * TILE_B + r * TSTR + ldc * 16;
            const __nv_bfloat16* src = tiles[t] + (size_t)(row0s[t] + r) * K + ldc * 8;
            CP_ASYNC16(dst, src);
        }
    CP_COMMIT();
    CP_WAIT0();
    __syncthreads();

    int a_row = (lane & 7) + ((lane >> 3) & 1) * 8;
    int a_kb  = ((lane >> 4) & 1) * 16;
    int b_row = (lane & 7) + ((lane >> 4) & 1) * 8;
    int b_kb  = ((lane >> 3) & 1) * 16;

    for (int kc = 0; kc < NC; kc++) {
        int b = kc & 1;
        uint32_t sbuf = sbase + b * BUF_B;
        if (kc + 1 < NC) {
            uint32_t dbuf = sbase + (b ^ 1) * BUF_B;
            int k0 = (kc + 1) * 32;
            #pragma unroll
            for (int t = 0; t < 4; t++)
                #pragma unroll
                for (int it = 0; it < 2; it++) {
                    int r = it * 64 + ldr;
                    uint32_t dst = dbuf + t * TILE_B + r * TSTR + ldc * 16;
                    const __nv_bfloat16* src = tiles[t] + (size_t)(row0s[t] + r) * K + k0 + ldc * 8;
                    CP_ASYNC16(dst, src);
                }
            CP_COMMIT();
        }

        #pragma unroll
        for (int ks = 0; ks < 2; ks++) {
            int kb = ks * 32;
            uint32_t ah[2][4], al[2][4];
            #pragma unroll
            for (int mt = 0; mt < 2; mt++) {
                uint32_t addr = sbuf + (warp_m * 32 + mt * 16 + a_row) * TSTR + kb + a_kb;
                ldsm_x4(ah[mt][0], ah[mt][1], ah[mt][2], ah[mt][3], addr);
                ldsm_x4(al[mt][0], al[mt][1], al[mt][2], al[mt][3], addr + TILE_B);
            }
            #pragma unroll
            for (int nb = 0; nb < 4; nb++) {
                uint32_t addr = sbuf + 2 * TILE_B +
                                (warp_n * 64 + nb * 16 + b_row) * TSTR + kb + b_kb;
                uint32_t bh0, bh1, bh2, bh3, bl0, bl1, bl2, bl3;
                ldsm_x4(bh0, bh1, bh2, bh3, addr);
                ldsm_x4(bl0, bl1, bl2, bl3, addr + TILE_B);
                #pragma unroll
                for (int mt = 0; mt < 2; mt++) {
                    float* e = acc[mt][nb * 2];
                    float* o = acc[mt][nb * 2 + 1];
                    mma_bf16(e, ah[mt][0], ah[mt][1], ah[mt][2], ah[mt][3], bh0, bh1);
                    mma_bf16(e, ah[mt][0], ah[mt][1], ah[mt][2], ah[mt][3], bl0, bl1);
                    mma_bf16(e, al[mt][0], al[mt][1], al[mt][2], al[mt][3], bh0, bh1);
                    mma_bf16(o, ah[mt][0], ah[mt][1], ah[mt][2], ah[mt][3], bh2, bh3);
                    mma_bf16(o, ah[mt][0], ah[mt][1], ah[mt][2], ah[mt][3], bl2, bl3);
                    mma_bf16(o, al[mt][0], al[mt][1], al[mt][2], al[mt][3], bh2, bh3);
                }
            }
        }
        if (kc + 1 < NC) CP_WAIT0();
        __syncthreads();
    }

    #pragma unroll
    for (int mt = 0; mt < 2; mt++) {
        #pragma unroll
        for (int nt = 0; nt < 8; nt++) {
            int cl = warp_n * 64 + nt * 8 + (lane & 3) * 2;   // local col 0..127
            int col = n0 + cl;
            #pragma unroll
            for (int half = 0; half < 2; half++) {
                int row = m0 + warp_m * 32 + mt * 16 + (lane >> 2) + half * 8;
                float v0 = acc[mt][nt][half * 2 + 0] + biasP[cl + 0];
                float v1 = acc[mt][nt][half * 2 + 1] + biasP[cl + 1];
                if (outF) {
                    if (R) {
                        const float2 rv = *(const float2*)(R + (size_t)row * N + col);
                        v0 += rv.x; v1 += rv.y;
                    }
                    float2 o2; o2.x = v0; o2.y = v1;
                    *(float2*)(outF + (size_t)row * N + col) = o2;
                } else {
                    if (act) { v0 = gelu_exact(v0); v1 = gelu_exact(v1); }
                    __nv_bfloat16 h0, h1, l0, l1;
                    split_bf16(v0, h0, l0);
                    split_bf16(v1, h1, l1);
                    __nv_bfloat162 hh; hh.x = h0; hh.y = h1;
                    __nv_bfloat162 ll; ll.x = l0; ll.y = l1;
                    *(__nv_bfloat162*)(outH + osel + (size_t)row * N + col) = hh;
                    *(__nv_bfloat162*)(outL + osel + (size_t)row * N + col) = ll;
                }
            }
        }
    }
}

// ================= HMMA flash attention =====================================
#define ATS 144
#define ATTN_SMEM (2 * 128 * ATS + 4 * 64 * ATS)

__global__ __launch_bounds__(256) void attn_tc(
    const __nv_bfloat16* __restrict__ qh, const __nv_bfloat16* __restrict__ ql,
    const __nv_bfloat16* __restrict__ kh, const __nv_bfloat16* __restrict__ kl,
    const __nv_bfloat16* __restrict__ vh, const __nv_bfloat16* __restrict__ vl,
    __nv_bfloat16* __restrict__ oh, __nv_bfloat16* __restrict__ ol) {
    extern __shared__ char sm[];
    uint32_t sb = smem_to_u32(sm);
    uint32_t sQh = sb;
    uint32_t sQl = sb + 128 * ATS;
    uint32_t sKh = sb + 2 * 128 * ATS;
    uint32_t sKl = sKh + 64 * ATS;
    uint32_t sVh = sKl + 64 * ATS;
    uint32_t sVl = sVh + 64 * ATS;

    int qb = blockIdx.x, bh = blockIdx.y;
    int b = bh >> 4, h = bh & 15;
    int q0 = qb * 128;
    int tid = threadIdx.x, wid = tid >> 5, lane = tid & 31;
    int g = lane >> 2, t4 = lane & 3;

    size_t base = ((size_t)b * TSEQ) * CDIM + (size_t)h * HDIM;

    #pragma unroll
    for (int i = 0; i < 4; i++) {
        int idx = i * 256 + tid;
        int r = idx >> 3, c = idx & 7;
        size_t gsrc = base + (size_t)(q0 + r) * CDIM + c * 8;
        CP_ASYNC16(sQh + r * ATS + c * 16, qh + gsrc);
        CP_ASYNC16(sQl + r * ATS + c * 16, ql + gsrc);
    }
    CP_COMMIT();
    CP_WAIT0();
    __syncthreads();

    int a_row = (lane & 7) + ((lane >> 3) & 1) * 8;
    int a_kb  = ((lane >> 4) & 1) * 16;
    int b_row = (lane & 7) + ((lane >> 4) & 1) * 8;
    int b_kb  = ((lane >> 3) & 1) * 16;
    int v_row = (lane & 7) + ((lane >> 3) & 1) * 8;
    int v_cb  = ((lane >> 4) & 1) * 16;

    uint32_t qfh[4][4], qfl[4][4];
    #pragma unroll
    for (int ks = 0; ks < 4; ks++) {
        uint32_t ad = sQh + (wid * 16 + a_row) * ATS + ks * 32 + a_kb;
        ldsm_x4(qfh[ks][0], qfh[ks][1], qfh[ks][2], qfh[ks][3], ad);
        ldsm_x4(qfl[ks][0], qfl[ks][1], qfl[ks][2], qfl[ks][3], ad + 128 * ATS);
    }

    float oacc[8][4];
    #pragma unroll
    for (int i = 0; i < 8; i++)
        #pragma unroll
        for (int c = 0; c < 4; c++) oacc[i][c] = 0.f;
    float mrun0 = -1e30f, mrun1 = -1e30f, lrun0 = 0.f, lrun1 = 0.f;

    int nkt = 2 * qb + 2;
    for (int kt = 0; kt < nkt; kt++) {
        __syncthreads();
        #pragma unroll
        for (int i = 0; i < 2; i++) {
            int idx = i * 256 + tid;
            int r = idx >> 3, c = idx & 7;
            size_t gsrc = base + (size_t)(kt * 64 + r) * CDIM + c * 8;
            uint32_t so = r * ATS + c * 16;
            CP_ASYNC16(sKh + so, kh + gsrc);
            CP_ASYNC16(sKl + so, kl + gsrc);
            CP_ASYNC16(sVh + so, vh + gsrc);
            CP_ASYNC16(sVl + so, vl + gsrc);
        }
        CP_COMMIT();
        CP_WAIT0();
        __syncthreads();

        float sacc[8][4];
        #pragma unroll
        for (int i = 0; i < 8; i++)
            #pragma unroll
            for (int c = 0; c < 4; c++) sacc[i][c] = 0.f;

        #pragma unroll
        for (int kg = 0; kg < 4; kg++) {
            #pragma unroll
            for (int ks = 0; ks < 4; ks++) {
                uint32_t ad = sKh + (kg * 16 + b_row) * ATS + ks * 32 + b_kb;
                uint32_t kh0, kh1, kh2, kh3, kl0, kl1, kl2, kl3;
                ldsm_x4(kh0, kh1, kh2, kh3, ad);
                ldsm_x4(kl0, kl1, kl2, kl3, ad + 64 * ATS);
                float* e = sacc[kg * 2];
                float* o = sacc[kg * 2 + 1];
                mma_bf16(e, qfh[ks][0], qfh[ks][1], qfh[ks][2], qfh[ks][3], kh0, kh1);
                mma_bf16(e, qfh[ks][0], qfh[ks][1], qfh[ks][2], qfh[ks][3], kl0, kl1);
                mma_bf16(e, qfl[ks][0], qfl[ks][1], qfl[ks][2], qfl[ks][3], kh0, kh1);
                mma_bf16(o, qfh[ks][0], qfh[ks][1], qfh[ks][2], qfh[ks][3], kh2, kh3);
                mma_bf16(o, qfh[ks][0], qfh[ks][1], qfh[ks][2], qfh[ks][3], kl2, kl3);
                mma_bf16(o, qfl[ks][0], qfl[ks][1], qfl[ks][2], qfl[ks][3], kh2, kh3);
            }
        }

        int r0g = q0 + wid * 16 + g;
        int r1g = r0g + 8;
        bool maskt = (kt >= 2 * qb);
        #pragma unroll
        for (int nt = 0; nt < 8; nt++) {
            #pragma unroll
            for (int c = 0; c < 4; c++) sacc[nt][c] *= 0.125f;
            if (maskt) {
                int cb = kt * 64 + nt * 8 + 2 * t4;
                if (cb     > r0g) sacc[nt][0] = -1e30f;
                if (cb + 1 > r0g) sacc[nt][1] = -1e30f;
                if (cb     > r1g) sacc[nt][2] = -1e30f;
                if (cb + 1 > r1g) sacc[nt][3] = -1e30f;
            }
        }

        float mt0 = -1e30f, mt1 = -1e30f;
        #pragma unroll
        for (int nt = 0; nt < 8; nt++) {
            mt0 = fmaxf(mt0, fmaxf(sacc[nt][0], sacc[nt][1]));
            mt1 = fmaxf(mt1, fmaxf(sacc[nt][2], sacc[nt][3]));
        }
        mt0 = fmaxf(mt0, __shfl_xor_sync(0xffffffffu, mt0, 1));
        mt0 = fmaxf(mt0, __shfl_xor_sync(0xffffffffu, mt0, 2));
        mt1 = fmaxf(mt1, __shfl_xor_sync(0xffffffffu, mt1, 1));
        mt1 = fmaxf(mt1, __shfl_xor_sync(0xffffffffu, mt1, 2));

        float mn0 = fmaxf(mrun0, mt0), mn1 = fmaxf(mrun1, mt1);
        float cr0 = __expf(mrun0 - mn0), cr1 = __expf(mrun1 - mn1);
        mrun0 = mn0; mrun1 = mn1;
        #pragma unroll
        for (int nt = 0; nt < 8; nt++) {
            oacc[nt][0] *= cr0; oacc[nt][1] *= cr0;
            oacc[nt][2] *= cr1; oacc[nt][3] *= cr1;
        }
        lrun0 *= cr0; lrun1 *= cr1;

        float ls0 = 0.f, ls1 = 0.f;
        #pragma unroll
        for (int nt = 0; nt < 8; nt++) {
            sacc[nt][0] = __expf(sacc[nt][0] - mn0);
            sacc[nt][1] = __expf(sacc[nt][1] - mn0);
            sacc[nt][2] = __expf(sacc[nt][2] - mn1);
            sacc[nt][3] = __expf(sacc[nt][3] - mn1);
            ls0 += sacc[nt][0] + sacc[nt][1];
            ls1 += sacc[nt][2] + sacc[nt][3];
        }
        ls0 += __shfl_xor_sync(0xffffffffu, ls0, 1);
        ls0 += __shfl_xor_sync(0xffffffffu, ls0, 2);
        ls1 += __shfl_xor_sync(0xffffffffu, ls1, 1);
        ls1 += __shfl_xor_sync(0xffffffffu, ls1, 2);
        lrun0 += ls0; lrun1 += ls1;

        #pragma unroll
        for (int s = 0; s < 4; s++) {
            uint32_t aPh[4], aPl[4];
            splitpack(sacc[2 * s][0],     sacc[2 * s][1],     aPh[0], aPl[0]);
            splitpack(sacc[2 * s][2],     sacc[2 * s][3],     aPh[1], aPl[1]);
            splitpack(sacc[2 * s + 1][0], sacc[2 * s + 1][1], aPh[2], aPl[2]);
            splitpack(sacc[2 * s + 1][2], sacc[2 * s + 1][3], aPh[3], aPl[3]);
            #pragma unroll
            for (int p = 0; p < 4; p++) {
                uint32_t ad = sVh + (s * 16 + v_row) * ATS + p * 32 + v_cb;
                uint32_t vh0, vh1, vh2, vh3, vl0, vl1, vl2, vl3;
                ldsm_x4_trans(vh0, vh1, vh2, vh3, ad);
                ldsm_x4_trans(vl0, vl1, vl2, vl3, ad + 64 * ATS);
                float* e = oacc[p * 2];
                float* o = oacc[p * 2 + 1];
                mma_bf16(e, aPh[0], aPh[1], aPh[2], aPh[3], vh0, vh1);
                mma_bf16(e, aPl[0], aPl[1], aPl[2], aPl[3], vh0, vh1);
                mma_bf16(e, aPh[0], aPh[1], aPh[2], aPh[3], vl0, vl1);
                mma_bf16(o, aPh[0], aPh[1], aPh[2], aPh[3], vh2, vh3);
                mma_bf16(o, aPl[0], aPl[1], aPl[2], aPl[3], vh2, vh3);
                mma_bf16(o, aPh[0], aPh[1], aPh[2], aPh[3], vl2, vl3);
            }
        }
    }

    float il0 = 1.0f / lrun0, il1 = 1.0f / lrun1;
    int r0g = q0 + wid * 16 + g;
    #pragma unroll
    for (int nt = 0; nt < 8; nt++) {
        int col = nt * 8 + 2 * t4;
        float v0 = oacc[nt][0] * il0, v1 = oacc[nt][1] * il0;
        float v2 = oacc[nt][2] * il1, v3 = oacc[nt][3] * il1;
        __nv_bfloat16 h0, h1, h2, h3, l0, l1, l2, l3;
        split_bf16(v0, h0, l0); split_bf16(v1, h1, l1);
        split_bf16(v2, h2, l2); split_bf16(v3, h3, l3);
        size_t o0 = base + (size_t)r0g * CDIM + col;
        size_t o1 = base + (size_t)(r0g + 8) * CDIM + col;
        __nv_bfloat162 t;
        t.x = h0; t.y = h1; *(__nv_bfloat162*)(oh + o0) = t;
        t.x = l0; t.y = l1; *(__nv_bfloat162*)(ol + o0) = t;
        t.x = h2; t.y = h3; *(__nv_bfloat162*)(oh + o1) = t;
        t.x = l2; t.y = l3; *(__nv_bfloat162*)(ol + o1) = t;
    }
}

// ================= launch ====================================================
extern "C" void kernel_launch(void* const* d_in, const int* in_sizes, int n_in,
                              void* d_out, int out_size) {
    const float* x   = (const float*)d_in[0];
    const float* Wq  = (const float*)d_in[1];
    const float* bq  = (const float*)d_in[2];
    const float* Wk  = (const float*)d_in[3];
    const float* bk  = (const float*)d_in[4];
    const float* Wv  = (const float*)d_in[5];
    const float* bv  = (const float*)d_in[6];
    const float* Wp  = (const float*)d_in[7];
    const float* bp  = (const float*)d_in[8];
    const float* W1  = (const float*)d_in[9];
    const float* b1  = (const float*)d_in[10];
    const float* W2  = (const float*)d_in[11];
    const float* b2  = (const float*)d_in[12];
    const float* g1  = (const float*)d_in[13];
    const float* be1 = (const float*)d_in[14];
    const float* g2  = (const float*)d_in[15];
    const float* be2 = (const float*)d_in[16];
    float* out = (float*)d_out;

    unsigned char* S;
    cudaGetSymbolAddress((void**)&S, g_scratch);
    __nv_bfloat16* qhB = (__nv_bfloat16*)(S + OFF_QH);
    __nv_bfloat16* qlB = (__nv_bfloat16*)(S + OFF_QL);
    __nv_bfloat16* khB = (__nv_bfloat16*)(S + OFF_KH);
    __nv_bfloat16* klB = (__nv_bfloat16*)(S + OFF_KL);
    __nv_bfloat16* vhB = (__nv_bfloat16*)(S + OFF_VH);
    __nv_bfloat16* vlB = (__nv_bfloat16*)(S + OFF_VL);
    float* yb  = (float*)(S + OFF_Y);
    __nv_bfloat16* ln1h = (__nv_bfloat16*)(S + OFF_LN1H);
    __nv_bfloat16* ln1l = (__nv_bfloat16*)(S + OFF_LN1L);
    __nv_bfloat16* atth = (__nv_bfloat16*)(S + OFF_ATTH);
    __nv_bfloat16* attl = (__nv_bfloat16*)(S + OFF_ATTL);
    __nv_bfloat16* ln2h = (__nv_bfloat16*)(S + OFF_LN2H);
    __nv_bfloat16* ln2l = (__nv_bfloat16*)(S + OFF_LN2L);
    __nv_bfloat16* ffh  = (__nv_bfloat16*)(S + OFF_FFH);
    __nv_bfloat16* ffl  = (__nv_bfloat16*)(S + OFF_FFL);
    __nv_bfloat16* wqkvh = (__nv_bfloat16*)(S + OFF_WQKVH);
    __nv_bfloat16* wqkvl = (__nv_bfloat16*)(S + OFF_WQKVL);
    __nv_bfloat16* wph = (__nv_bfloat16*)(S + OFF_WPH);
    __nv_bfloat16* wpl = (__nv_bfloat16*)(S + OFF_WPL);
    __nv_bfloat16* w1h = (__nv_bfloat16*)(S + OFF_W1H);
    __nv_bfloat16* w1l = (__nv_bfloat16*)(S + OFF_W1L);
    __nv_bfloat16* w2h = (__nv_bfloat16*)(S + OFF_W2H);
    __nv_bfloat16* w2l = (__nv_bfloat16*)(S + OFF_W2L);
    float* biasC = (float*)(S + OFF_BIASC);

    cudaFuncSetAttribute(attn_tc, cudaFuncAttributeMaxDynamicSharedMemorySize, ATTN_SMEM);
    cudaFuncSetAttribute(gemm_tc, cudaFuncAttributeMaxDynamicSharedMemorySize, GEMM_SMEM);

    // concat qkv biases (kernel, not memcpy: keep capture to pure launches)
    bias_concat_kernel<<<3, 1024>>>(bq, bk, bv, biasC);

    // weights -> bf16 hi/lo transposed; qkv into concat [3072,1024]
    wconv_kernel<<<dim3(16, 16), 256>>>(Wq, wqkvh,                wqkvl,                1024, 1024);
    wconv_kernel<<<dim3(16, 16), 256>>>(Wk, wqkvh + 1024 * 1024,  wqkvl + 1024 * 1024,  1024, 1024);
    wconv_kernel<<<dim3(16, 16), 256>>>(Wv, wqkvh + 2048 * 1024,  wqkvl + 2048 * 1024,  1024, 1024);
    wconv_kernel<<<dim3(16, 16), 256>>>(Wp, wph, wpl, 1024, 1024);
    wconv_kernel<<<dim3(16, 64), 256>>>(W1, w1h, w1l, 1024, 4096);
    wconv_kernel<<<dim3(64, 16), 256>>>(W2, w2h, w2l, 4096, 1024);

    ln_kernel<<<NROWS, 256>>>(x, g1, be1, ln1h, ln1l);

    dim3 gQKV(24, 32);  // 768 blocks
    dim3 gQ(8, 32);
    dim3 gF1(32, 32);
    gemm_tc<<<gQKV, 256, GEMM_SMEM>>>(ln1h, ln1l, wqkvh, wqkvl, biasC, nullptr,
                                      nullptr, qhB, qlB, 1024, 1024, 0, 1);

    attn_tc<<<dim3(TSEQ / 128, 4 * NHEADS), 256, ATTN_SMEM>>>(qhB, qlB, khB, klB, vhB, vlB, atth, attl);

    gemm_tc<<<gQ, 256, GEMM_SMEM>>>(atth, attl, wph, wpl, bp, x, yb, nullptr, nullptr, 1024, 1024, 0, 0);

    ln_kernel<<<NROWS, 256>>>(yb, g2, be2, ln2h, ln2l);

    gemm_tc<<<gF1, 256, GEMM_SMEM>>>(ln2h, ln2l, w1h, w1l, b1, nullptr, nullptr, ffh, ffl, 1024, 4096, 1, 0);
    gemm_tc<<<gQ, 256, GEMM_SMEM>>>(ffh, ffl, w2h, w2l, b2, yb, out, nullptr, nullptr, 4096, 1024, 0, 0);
}

// round 11
// speedup vs baseline: 2.5205x; 1.0152x over previous
#include <cuda_runtime.h>
#include <cuda_bf16.h>
#include <cstdint>
#include <math.h>

#define NROWS 4096      // B*T
#define CDIM  1024
#define HDIM  64
#define NHEADS 16
#define TSEQ  1024
#define FFDIM 4096

// ================= helpers ==================================================
__device__ __forceinline__ uint32_t smem_to_u32(const void* p) {
    uint32_t a;
    asm("{ .reg .u64 t; cvta.to.shared.u64 t, %1; cvt.u32.u64 %0, t; }"
        : "=r"(a) : "l"(p));
    return a;
}
__device__ __forceinline__ void ldsm_x4(uint32_t& r0, uint32_t& r1,
                                        uint32_t& r2, uint32_t& r3, uint32_t a) {
    asm volatile("ldmatrix.sync.aligned.m8n8.x4.shared.b16 {%0,%1,%2,%3}, [%4];"
                 : "=r"(r0), "=r"(r1), "=r"(r2), "=r"(r3) : "r"(a));
}
__device__ __forceinline__ void ldsm_x4_trans(uint32_t& r0, uint32_t& r1,
                                              uint32_t& r2, uint32_t& r3, uint32_t a) {
    asm volatile("ldmatrix.sync.aligned.m8n8.x4.trans.shared.b16 {%0,%1,%2,%3}, [%4];"
                 : "=r"(r0), "=r"(r1), "=r"(r2), "=r"(r3) : "r"(a));
}
__device__ __forceinline__ void mma_bf16(float* d,
                                         uint32_t a0, uint32_t a1, uint32_t a2, uint32_t a3,
                                         uint32_t b0, uint32_t b1) {
    asm volatile("mma.sync.aligned.m16n8k16.row.col.f32.bf16.bf16.f32 "
                 "{%0,%1,%2,%3}, {%4,%5,%6,%7}, {%8,%9}, {%0,%1,%2,%3};"
                 : "+f"(d[0]), "+f"(d[1]), "+f"(d[2]), "+f"(d[3])
                 : "r"(a0), "r"(a1), "r"(a2), "r"(a3), "r"(b0), "r"(b1));
}
#define CP_ASYNC16(dst, src) \
    asm volatile("cp.async.cg.shared.global [%0], [%1], 16;" :: "r"(dst), "l"(src))
#define CP_COMMIT() asm volatile("cp.async.commit_group;" ::: "memory")
#define CP_WAIT0()  asm volatile("cp.async.wait_group 0;" ::: "memory")

__device__ __forceinline__ void split_bf16(float v, __nv_bfloat16& h, __nv_bfloat16& l) {
    h = __float2bfloat16(v);
    l = __float2bfloat16(v - __bfloat162float(h));
}
__device__ __forceinline__ uint32_t packh(__nv_bfloat16 a, __nv_bfloat16 b) {
    __nv_bfloat162 t; t.x = a; t.y = b;
    return *(uint32_t*)&t;
}
__device__ __forceinline__ void splitpack(float v0, float v1, uint32_t& ph, uint32_t& pl) {
    __nv_bfloat16 h0 = __float2bfloat16(v0), h1 = __float2bfloat16(v1);
    ph = packh(h0, h1);
    float l0 = v0 - __bfloat162float(h0), l1 = v1 - __bfloat162float(h1);
    asm("cvt.rn.bf16x2.f32 %0, %1, %2;" : "=r"(pl) : "f"(l1), "f"(l0));
}
__device__ __forceinline__ float gelu_exact(float v) {
    return 0.5f * v * (1.0f + erff(v * 0.70710678118654752f));
}

// ================= scratch ==================================================
#define MB (1024ull * 1024ull)
__device__ __align__(1024) unsigned char g_scratch[225 * MB];
#define OFF_QH    (0 * MB)
#define OFF_QL    (8 * MB)
#define OFF_KH    (16 * MB)
#define OFF_KL    (24 * MB)
#define OFF_VH    (32 * MB)
#define OFF_VL    (40 * MB)
#define OFF_Y     (48 * MB)
#define OFF_LN1H  (64 * MB)
#define OFF_LN1L  (72 * MB)
#define OFF_ATTH  (80 * MB)
#define OFF_ATTL  (88 * MB)
#define OFF_LN2H  (96 * MB)
#define OFF_LN2L  (104 * MB)
#define OFF_FFH   (112 * MB)
#define OFF_FFL   (144 * MB)
#define OFF_WQKVH (176 * MB)   // [3072,1024] bf16 = 6MB
#define OFF_WQKVL (182 * MB)
#define OFF_WPH   (188 * MB)
#define OFF_WPL   (190 * MB)
#define OFF_W1H   (192 * MB)
#define OFF_W1L   (200 * MB)
#define OFF_W2H   (208 * MB)
#define OFF_W2L   (216 * MB)
#define OFF_BIASC (224 * MB)   // concat qkv bias [3072] f32
#define QKV_SEL_STRIDE 8388608ull   // 16MB / 2B: q->k->v buffer spacing in elements

// ================= bias concat ==============================================
__global__ __launch_bounds__(1024) void bias_concat_kernel(
    const float* __restrict__ bq, const float* __restrict__ bk,
    const float* __restrict__ bv, float* __restrict__ dst) {
    int i = threadIdx.x;
    const float* src = (blockIdx.x == 0) ? bq : (blockIdx.x == 1) ? bk : bv;
    dst[blockIdx.x * 1024 + i] = src[i];
}

// ================= fused weight convert+transpose (ALL weights, 1 launch) ===
// Block ranges: [0,256) Wq | [256,512) Wk | [512,768) Wv | [768,1024) Wp |
// [1024,2048) W1 (16x64) | [2048,3072) W2 (64x16). 64x64 tile per block.
__global__ __launch_bounds__(256) void wconv_all(
    const float* __restrict__ Wq, const float* __restrict__ Wk,
    const float* __restrict__ Wv, const float* __restrict__ Wp,
    const float* __restrict__ W1, const float* __restrict__ W2,
    __nv_bfloat16* __restrict__ qkvh, __nv_bfloat16* __restrict__ qkvl,
    __nv_bfloat16* __restrict__ wph,  __nv_bfloat16* __restrict__ wpl,
    __nv_bfloat16* __restrict__ w1h,  __nv_bfloat16* __restrict__ w1l,
    __nv_bfloat16* __restrict__ w2h,  __nv_bfloat16* __restrict__ w2l) {
    int bid = blockIdx.x;
    const float* W; __nv_bfloat16 *Wh, *Wl;
    int K, N, bx, by;
    if (bid < 768) {                       // Wq/Wk/Wv -> concat
        int which = bid >> 8;
        int idx = bid & 255;
        W = (which == 0) ? Wq : (which == 1) ? Wk : Wv;
        Wh = qkvh + (size_t)which * 1024 * 1024;
        Wl = qkvl + (size_t)which * 1024 * 1024;
        K = 1024; N = 1024; bx = idx & 15; by = idx >> 4;
    } else if (bid < 1024) {
        int idx = bid - 768;
        W = Wp; Wh = wph; Wl = wpl;
        K = 1024; N = 1024; bx = idx & 15; by = idx >> 4;
    } else if (bid < 2048) {
        int idx = bid - 1024;
        W = W1; Wh = w1h; Wl = w1l;
        K = 1024; N = 4096; bx = idx & 15; by = idx >> 4;
    } else {
        int idx = bid - 2048;
        W = W2; Wh = w2h; Wl = w2l;
        K = 4096; N = 1024; bx = idx & 63; by = idx >> 6;
    }

    __shared__ float t[64][65];
    int k0 = bx * 64, n0 = by * 64;
    int tid = threadIdx.x;
    #pragma unroll
    for (int i = 0; i < 16; i++) {
        int idx = i * 256 + tid;
        int r = idx >> 6, c = idx & 63;
        t[r][c] = W[(size_t)(k0 + r) * N + n0 + c];
    }
    __syncthreads();
    #pragma unroll
    for (int i = 0; i < 16; i++) {
        int idx = i * 256 + tid;
        int r = idx >> 6, c = idx & 63;
        float v = t[c][r];
        __nv_bfloat16 h, l;
        split_bf16(v, h, l);
        size_t o = (size_t)(n0 + r) * K + k0 + c;
        Wh[o] = h; Wl[o] = l;
    }
}

// ================= layernorm -> bf16 hi/lo ==================================
__global__ __launch_bounds__(256) void ln_kernel(const float* __restrict__ x,
                                                 const float* __restrict__ g,
                                                 const float* __restrict__ b,
                                                 __nv_bfloat16* __restrict__ H,
                                                 __nv_bfloat16* __restrict__ L) {
    int row = blockIdx.x;
    int t = threadIdx.x;
    const float4* xr = (const float4*)(x + (size_t)row * CDIM);
    float4 xv = xr[t];
    float s  = xv.x + xv.y + xv.z + xv.w;
    float ss = xv.x * xv.x + xv.y * xv.y + xv.z * xv.z + xv.w * xv.w;
    #pragma unroll
    for (int m = 16; m; m >>= 1) {
        s  += __shfl_xor_sync(0xffffffffu, s,  m);
        ss += __shfl_xor_sync(0xffffffffu, ss, m);
    }
    __shared__ float rs[8], rss[8];
    int warp = t >> 5, lane = t & 31;
    if (lane == 0) { rs[warp] = s; rss[warp] = ss; }
    __syncthreads();
    float tot = 0.f, tots = 0.f;
    #pragma unroll
    for (int i = 0; i < 8; i++) { tot += rs[i]; tots += rss[i]; }
    float mu  = tot * (1.0f / CDIM);
    float var = tots * (1.0f / CDIM) - mu * mu;
    float inv = rsqrtf(var + 1e-5f);
    float4 gv = ((const float4*)g)[t];
    float4 bv = ((const float4*)b)[t];
    float o0 = (xv.x - mu) * inv * gv.x + bv.x;
    float o1 = (xv.y - mu) * inv * gv.y + bv.y;
    float o2 = (xv.z - mu) * inv * gv.z + bv.z;
    float o3 = (xv.w - mu) * inv * gv.w + bv.w;
    __nv_bfloat16 h0, h1, h2, h3, l0, l1, l2, l3;
    split_bf16(o0, h0, l0); split_bf16(o1, h1, l1);
    split_bf16(o2, h2, l2); split_bf16(o3, h3, l3);
    __nv_bfloat162* Hp = (__nv_bfloat162*)(H + (size_t)row * CDIM + t * 4);
    __nv_bfloat162* Lp = (__nv_bfloat162*)(L + (size_t)row * CDIM + t * 4);
    __nv_bfloat162 a01; a01.x = h0; a01.y = h1;
    __nv_bfloat162 a23; a23.x = h2; a23.y = h3;
    __nv_bfloat162 b01; b01.x = l0; b01.y = l1;
    __nv_bfloat162 b23; b23.x = l2; b23.y = l3;
    Hp[0] = a01; Hp[1] = a23;
    Lp[0] = b01; Lp[1] = b23;
}

// ================= HMMA bf16x3 GEMM =========================================
#define TSTR 80
#define TILE_B (128 * TSTR)
#define BUF_B  (4 * TILE_B)
#define GEMM_SMEM (2 * BUF_B)

__global__ __launch_bounds__(256, 2) void gemm_tc(
    const __nv_bfloat16* __restrict__ Ah, const __nv_bfloat16* __restrict__ Al,
    const __nv_bfloat16* __restrict__ Bh, const __nv_bfloat16* __restrict__ Bl,
    const float* __restrict__ bias, const float* __restrict__ R,
    float* __restrict__ outF, __nv_bfloat16* __restrict__ outH,
    __nv_bfloat16* __restrict__ outL, int K, int N, int act, int qkv) {
    extern __shared__ char sm[];
    uint32_t sbase = smem_to_u32(sm);
    int tid = threadIdx.x;
    int wid = tid >> 5, lane = tid & 31;
    int warp_m = wid & 3, warp_n = wid >> 2;
    int bx = blockIdx.x;
    int wrow0 = bx * 128;                       // weight rows (concat space)
    int n0 = qkv ? ((bx & 7) * 128) : wrow0;    // output col base
    const float* biasP = bias + (qkv ? bx * 128 : n0);
    size_t osel = qkv ? (size_t)(bx >> 3) * QKV_SEL_STRIDE : 0;
    int m0 = blockIdx.y * 128;
    int NC = K >> 5;

    float acc[2][8][4];
    #pragma unroll
    for (int i = 0; i < 2; i++)
        #pragma unroll
        for (int j = 0; j < 8; j++)
            #pragma unroll
            for (int c = 0; c < 4; c++) acc[i][j][c] = 0.f;

    const __nv_bfloat16* tiles[4] = {Ah, Al, Bh, Bl};
    int row0s[4] = {m0, m0, wrow0, wrow0};
    int ldr = tid >> 2;
    int ldc = tid & 3;

    #pragma unroll
    for (int t = 0; t < 4; t++)
        #pragma unroll
        for (int it = 0; it < 2; it++) {
            int r = it * 64 + ldr;
            uint32_t dst = sbase + t * TILE_B + r * TSTR + ldc * 16;
            const __nv_bfloat16* src = tiles[t] + (size_t)(row0s[t] + r) * K + ldc * 8;
            CP_ASYNC16(dst, src);
        }
    CP_COMMIT();
    CP_WAIT0();
    __syncthreads();

    int a_row = (lane & 7) + ((lane >> 3) & 1) * 8;
    int a_kb  = ((lane >> 4) & 1) * 16;
    int b_row = (lane & 7) + ((lane >> 4) & 1) * 8;
    int b_kb  = ((lane >> 3) & 1) * 16;

    for (int kc = 0; kc < NC; kc++) {
        int b = kc & 1;
        uint32_t sbuf = sbase + b * BUF_B;
        if (kc + 1 < NC) {
            uint32_t dbuf = sbase + (b ^ 1) * BUF_B;
            int k0 = (kc + 1) * 32;
            #pragma unroll
            for (int t = 0; t < 4; t++)
                #pragma unroll
                for (int it = 0; it < 2; it++) {
                    int r = it * 64 + ldr;
                    uint32_t dst = dbuf + t * TILE_B + r * TSTR + ldc * 16;
                    const __nv_bfloat16* src = tiles[t] + (size_t)(row0s[t] + r) * K + k0 + ldc * 8;
                    CP_ASYNC16(dst, src);
                }
            CP_COMMIT();
        }

        #pragma unroll
        for (int ks = 0; ks < 2; ks++) {
            int kb = ks * 32;
            uint32_t ah[2][4], al[2][4];
            #pragma unroll
            for (int mt = 0; mt < 2; mt++) {
                uint32_t addr = sbuf + (warp_m * 32 + mt * 16 + a_row) * TSTR + kb + a_kb;
                ldsm_x4(ah[mt][0], ah[mt][1], ah[mt][2], ah[mt][3], addr);
                ldsm_x4(al[mt][0], al[mt][1], al[mt][2], al[mt][3], addr + TILE_B);
            }
            #pragma unroll
            for (int nb = 0; nb < 4; nb++) {
                uint32_t addr = sbuf + 2 * TILE_B +
                                (warp_n * 64 + nb * 16 + b_row) * TSTR + kb + b_kb;
                uint32_t bh0, bh1, bh2, bh3, bl0, bl1, bl2, bl3;
                ldsm_x4(bh0, bh1, bh2, bh3, addr);
                ldsm_x4(bl0, bl1, bl2, bl3, addr + TILE_B);
                #pragma unroll
                for (int mt = 0; mt < 2; mt++) {
                    float* e = acc[mt][nb * 2];
                    float* o = acc[mt][nb * 2 + 1];
                    mma_bf16(e, ah[mt][0], ah[mt][1], ah[mt][2], ah[mt][3], bh0, bh1);
                    mma_bf16(e, ah[mt][0], ah[mt][1], ah[mt][2], ah[mt][3], bl0, bl1);
                    mma_bf16(e, al[mt][0], al[mt][1], al[mt][2], al[mt][3], bh0, bh1);
                    mma_bf16(o, ah[mt][0], ah[mt][1], ah[mt][2], ah[mt][3], bh2, bh3);
                    mma_bf16(o, ah[mt][0], ah[mt][1], ah[mt][2], ah[mt][3], bl2, bl3);
                    mma_bf16(o, al[mt][0], al[mt][1], al[mt][2], al[mt][3], bh2, bh3);
                }
            }
        }
        if (kc + 1 < NC) CP_WAIT0();
        __syncthreads();
    }

    #pragma unroll
    for (int mt = 0; mt < 2; mt++) {
        #pragma unroll
        for (int nt = 0; nt < 8; nt++) {
            int cl = warp_n * 64 + nt * 8 + (lane & 3) * 2;   // local col 0..127
            int col = n0 + cl;
            #pragma unroll
            for (int half = 0; half < 2; half++) {
                int row = m0 + warp_m * 32 + mt * 16 + (lane >> 2) + half * 8;
                float v0 = acc[mt][nt][half * 2 + 0] + biasP[cl + 0];
                float v1 = acc[mt][nt][half * 2 + 1] + biasP[cl + 1];
                if (outF) {
                    if (R) {
                        const float2 rv = *(const float2*)(R + (size_t)row * N + col);
                        v0 += rv.x; v1 += rv.y;
                    }
                    float2 o2; o2.x = v0; o2.y = v1;
                    *(float2*)(outF + (size_t)row * N + col) = o2;
                } else {
                    if (act) { v0 = gelu_exact(v0); v1 = gelu_exact(v1); }
                    __nv_bfloat16 h0, h1, l0, l1;
                    split_bf16(v0, h0, l0);
                    split_bf16(v1, h1, l1);
                    __nv_bfloat162 hh; hh.x = h0; hh.y = h1;
                    __nv_bfloat162 ll; ll.x = l0; ll.y = l1;
                    *(__nv_bfloat162*)(outH + osel + (size_t)row * N + col) = hh;
                    *(__nv_bfloat162*)(outL + osel + (size_t)row * N + col) = ll;
                }
            }
        }
    }
}

// ================= HMMA flash attention =====================================
#define ATS 144
#define ATTN_SMEM (2 * 128 * ATS + 4 * 64 * ATS)

__global__ __launch_bounds__(256) void attn_tc(
    const __nv_bfloat16* __restrict__ qh, const __nv_bfloat16* __restrict__ ql,
    const __nv_bfloat16* __restrict__ kh, const __nv_bfloat16* __restrict__ kl,
    const __nv_bfloat16* __restrict__ vh, const __nv_bfloat16* __restrict__ vl,
    __nv_bfloat16* __restrict__ oh, __nv_bfloat16* __restrict__ ol) {
    extern __shared__ char sm[];
    uint32_t sb = smem_to_u32(sm);
    uint32_t sQh = sb;
    uint32_t sQl = sb + 128 * ATS;
    uint32_t sKh = sb + 2 * 128 * ATS;
    uint32_t sKl = sKh + 64 * ATS;
    uint32_t sVh = sKl + 64 * ATS;
    uint32_t sVl = sVh + 64 * ATS;

    // LPT: heaviest q-tiles (largest qb) launch first
    int qb = gridDim.x - 1 - blockIdx.x;
    int bh = blockIdx.y;
    int b = bh >> 4, h = bh & 15;
    int q0 = qb * 128;
    int tid = threadIdx.x, wid = tid >> 5, lane = tid & 31;
    int g = lane >> 2, t4 = lane & 3;

    size_t base = ((size_t)b * TSEQ) * CDIM + (size_t)h * HDIM;

    #pragma unroll
    for (int i = 0; i < 4; i++) {
        int idx = i * 256 + tid;
        int r = idx >> 3, c = idx & 7;
        size_t gsrc = base + (size_t)(q0 + r) * CDIM + c * 8;
        CP_ASYNC16(sQh + r * ATS + c * 16, qh + gsrc);
        CP_ASYNC16(sQl + r * ATS + c * 16, ql + gsrc);
    }
    CP_COMMIT();
    CP_WAIT0();
    __syncthreads();

    int a_row = (lane & 7) + ((lane >> 3) & 1) * 8;
    int a_kb  = ((lane >> 4) & 1) * 16;
    int b_row = (lane & 7) + ((lane >> 4) & 1) * 8;
    int b_kb  = ((lane >> 3) & 1) * 16;
    int v_row = (lane & 7) + ((lane >> 3) & 1) * 8;
    int v_cb  = ((lane >> 4) & 1) * 16;

    uint32_t qfh[4][4], qfl[4][4];
    #pragma unroll
    for (int ks = 0; ks < 4; ks++) {
        uint32_t ad = sQh + (wid * 16 + a_row) * ATS + ks * 32 + a_kb;
        ldsm_x4(qfh[ks][0], qfh[ks][1], qfh[ks][2], qfh[ks][3], ad);
        ldsm_x4(qfl[ks][0], qfl[ks][1], qfl[ks][2], qfl[ks][3], ad + 128 * ATS);
    }

    float oacc[8][4];
    #pragma unroll
    for (int i = 0; i < 8; i++)
        #pragma unroll
        for (int c = 0; c < 4; c++) oacc[i][c] = 0.f;
    float mrun0 = -1e30f, mrun1 = -1e30f, lrun0 = 0.f, lrun1 = 0.f;

    int nkt = 2 * qb + 2;
    for (int kt = 0; kt < nkt; kt++) {
        __syncthreads();
        #pragma unroll
        for (int i = 0; i < 2; i++) {
            int idx = i * 256 + tid;
            int r = idx >> 3, c = idx & 7;
            size_t gsrc = base + (size_t)(kt * 64 + r) * CDIM + c * 8;
            uint32_t so = r * ATS + c * 16;
            CP_ASYNC16(sKh + so, kh + gsrc);
            CP_ASYNC16(sKl + so, kl + gsrc);
            CP_ASYNC16(sVh + so, vh + gsrc);
            CP_ASYNC16(sVl + so, vl + gsrc);
        }
        CP_COMMIT();
        CP_WAIT0();
        __syncthreads();

        float sacc[8][4];
        #pragma unroll
        for (int i = 0; i < 8; i++)
            #pragma unroll
            for (int c = 0; c < 4; c++) sacc[i][c] = 0.f;

        #pragma unroll
        for (int kg = 0; kg < 4; kg++) {
            #pragma unroll
            for (int ks = 0; ks < 4; ks++) {
                uint32_t ad = sKh + (kg * 16 + b_row) * ATS + ks * 32 + b_kb;
                uint32_t kh0, kh1, kh2, kh3, kl0, kl1, kl2, kl3;
                ldsm_x4(kh0, kh1, kh2, kh3, ad);
                ldsm_x4(kl0, kl1, kl2, kl3, ad + 64 * ATS);
                float* e = sacc[kg * 2];
                float* o = sacc[kg * 2 + 1];
                mma_bf16(e, qfh[ks][0], qfh[ks][1], qfh[ks][2], qfh[ks][3], kh0, kh1);
                mma_bf16(e, qfh[ks][0], qfh[ks][1], qfh[ks][2], qfh[ks][3], kl0, kl1);
                mma_bf16(e, qfl[ks][0], qfl[ks][1], qfl[ks][2], qfl[ks][3], kh0, kh1);
                mma_bf16(o, qfh[ks][0], qfh[ks][1], qfh[ks][2], qfh[ks][3], kh2, kh3);
                mma_bf16(o, qfh[ks][0], qfh[ks][1], qfh[ks][2], qfh[ks][3], kl2, kl3);
                mma_bf16(o, qfl[ks][0], qfl[ks][1], qfl[ks][2], qfl[ks][3], kh2, kh3);
            }
        }

        int r0g = q0 + wid * 16 + g;
        int r1g = r0g + 8;
        bool maskt = (kt >= 2 * qb);
        #pragma unroll
        for (int nt = 0; nt < 8; nt++) {
            #pragma unroll
            for (int c = 0; c < 4; c++) sacc[nt][c] *= 0.125f;
            if (maskt) {
                int cb = kt * 64 + nt * 8 + 2 * t4;
                if (cb     > r0g) sacc[nt][0] = -1e30f;
                if (cb + 1 > r0g) sacc[nt][1] = -1e30f;
                if (cb     > r1g) sacc[nt][2] = -1e30f;
                if (cb + 1 > r1g) sacc[nt][3] = -1e30f;
            }
        }

        float mt0 = -1e30f, mt1 = -1e30f;
        #pragma unroll
        for (int nt = 0; nt < 8; nt++) {
            mt0 = fmaxf(mt0, fmaxf(sacc[nt][0], sacc[nt][1]));
            mt1 = fmaxf(mt1, fmaxf(sacc[nt][2], sacc[nt][3]));
        }
        mt0 = fmaxf(mt0, __shfl_xor_sync(0xffffffffu, mt0, 1));
        mt0 = fmaxf(mt0, __shfl_xor_sync(0xffffffffu, mt0, 2));
        mt1 = fmaxf(mt1, __shfl_xor_sync(0xffffffffu, mt1, 1));
        mt1 = fmaxf(mt1, __shfl_xor_sync(0xffffffffu, mt1, 2));

        float mn0 = fmaxf(mrun0, mt0), mn1 = fmaxf(mrun1, mt1);
        float cr0 = __expf(mrun0 - mn0), cr1 = __expf(mrun1 - mn1);
        mrun0 = mn0; mrun1 = mn1;
        #pragma unroll
        for (int nt = 0; nt < 8; nt++) {
            oacc[nt][0] *= cr0; oacc[nt][1] *= cr0;
            oacc[nt][2] *= cr1; oacc[nt][3] *= cr1;
        }
        lrun0 *= cr0; lrun1 *= cr1;

        float ls0 = 0.f, ls1 = 0.f;
        #pragma unroll
        for (int nt = 0; nt < 8; nt++) {
            sacc[nt][0] = __expf(sacc[nt][0] - mn0);
            sacc[nt][1] = __expf(sacc[nt][1] - mn0);
            sacc[nt][2] = __expf(sacc[nt][2] - mn1);
            sacc[nt][3] = __expf(sacc[nt][3] - mn1);
            ls0 += sacc[nt][0] + sacc[nt][1];
            ls1 += sacc[nt][2] + sacc[nt][3];
        }
        ls0 += __shfl_xor_sync(0xffffffffu, ls0, 1);
        ls0 += __shfl_xor_sync(0xffffffffu, ls0, 2);
        ls1 += __shfl_xor_sync(0xffffffffu, ls1, 1);
        ls1 += __shfl_xor_sync(0xffffffffu, ls1, 2);
        lrun0 += ls0; lrun1 += ls1;

        #pragma unroll
        for (int s = 0; s < 4; s++) {
            uint32_t aPh[4], aPl[4];
            splitpack(sacc[2 * s][0],     sacc[2 * s][1],     aPh[0], aPl[0]);
            splitpack(sacc[2 * s][2],     sacc[2 * s][3],     aPh[1], aPl[1]);
            splitpack(sacc[2 * s + 1][0], sacc[2 * s + 1][1], aPh[2], aPl[2]);
            splitpack(sacc[2 * s + 1][2], sacc[2 * s + 1][3], aPh[3], aPl[3]);
            #pragma unroll
            for (int p = 0; p < 4; p++) {
                uint32_t ad = sVh + (s * 16 + v_row) * ATS + p * 32 + v_cb;
                uint32_t vh0, vh1, vh2, vh3, vl0, vl1, vl2, vl3;
                ldsm_x4_trans(vh0, vh1, vh2, vh3, ad);
                ldsm_x4_trans(vl0, vl1, vl2, vl3, ad + 64 * ATS);
                float* e = oacc[p * 2];
                float* o = oacc[p * 2 + 1];
                mma_bf16(e, aPh[0], aPh[1], aPh[2], aPh[3], vh0, vh1);
                mma_bf16(e, aPl[0], aPl[1], aPl[2], aPl[3], vh0, vh1);
                mma_bf16(e, aPh[0], aPh[1], aPh[2], aPh[3], vl0, vl1);
                mma_bf16(o, aPh[0], aPh[1], aPh[2], aPh[3], vh2, vh3);
                mma_bf16(o, aPl[0], aPl[1], aPl[2], aPl[3], vh2, vh3);
                mma_bf16(o, aPh[0], aPh[1], aPh[2], aPh[3], vl2, vl3);
            }
        }
    }

    float il0 = 1.0f / lrun0, il1 = 1.0f / lrun1;
    int r0g = q0 + wid * 16 + g;
    #pragma unroll
    for (int nt = 0; nt < 8; nt++) {
        int col = nt * 8 + 2 * t4;
        float v0 = oacc[nt][0] * il0, v1 = oacc[nt][1] * il0;
        float v2 = oacc[nt][2] * il1, v3 = oacc[nt][3] * il1;
        __nv_bfloat16 h0, h1, h2, h3, l0, l1, l2, l3;
        split_bf16(v0, h0, l0); split_bf16(v1, h1, l1);
        split_bf16(v2, h2, l2); split_bf16(v3, h3, l3);
        size_t o0 = base + (size_t)r0g * CDIM + col;
        size_t o1 = base + (size_t)(r0g + 8) * CDIM + col;
        __nv_bfloat162 t;
        t.x = h0; t.y = h1; *(__nv_bfloat162*)(oh + o0) = t;
        t.x = l0; t.y = l1; *(__nv_bfloat162*)(ol + o0) = t;
        t.x = h2; t.y = h3; *(__nv_bfloat162*)(oh + o1) = t;
        t.x = l2; t.y = l3; *(__nv_bfloat162*)(ol + o1) = t;
    }
}

// ================= launch ====================================================
extern "C" void kernel_launch(void* const* d_in, const int* in_sizes, int n_in,
                              void* d_out, int out_size) {
    const float* x   = (const float*)d_in[0];
    const float* Wq  = (const float*)d_in[1];
    const float* bq  = (const float*)d_in[2];
    const float* Wk  = (const float*)d_in[3];
    const float* bk  = (const float*)d_in[4];
    const float* Wv  = (const float*)d_in[5];
    const float* bv  = (const float*)d_in[6];
    const float* Wp  = (const float*)d_in[7];
    const float* bp  = (const float*)d_in[8];
    const float* W1  = (const float*)d_in[9];
    const float* b1  = (const float*)d_in[10];
    const float* W2  = (const float*)d_in[11];
    const float* b2  = (const float*)d_in[12];
    const float* g1  = (const float*)d_in[13];
    const float* be1 = (const float*)d_in[14];
    const float* g2  = (const float*)d_in[15];
    const float* be2 = (const float*)d_in[16];
    float* out = (float*)d_out;

    unsigned char* S;
    cudaGetSymbolAddress((void**)&S, g_scratch);
    __nv_bfloat16* qhB = (__nv_bfloat16*)(S + OFF_QH);
    __nv_bfloat16* qlB = (__nv_bfloat16*)(S + OFF_QL);
    __nv_bfloat16* khB = (__nv_bfloat16*)(S + OFF_KH);
    __nv_bfloat16* klB = (__nv_bfloat16*)(S + OFF_KL);
    __nv_bfloat16* vhB = (__nv_bfloat16*)(S + OFF_VH);
    __nv_bfloat16* vlB = (__nv_bfloat16*)(S + OFF_VL);
    float* yb  = (float*)(S + OFF_Y);
    __nv_bfloat16* ln1h = (__nv_bfloat16*)(S + OFF_LN1H);
    __nv_bfloat16* ln1l = (__nv_bfloat16*)(S + OFF_LN1L);
    __nv_bfloat16* atth = (__nv_bfloat16*)(S + OFF_ATTH);
    __nv_bfloat16* attl = (__nv_bfloat16*)(S + OFF_ATTL);
    __nv_bfloat16* ln2h = (__nv_bfloat16*)(S + OFF_LN2H);
    __nv_bfloat16* ln2l = (__nv_bfloat16*)(S + OFF_LN2L);
    __nv_bfloat16* ffh  = (__nv_bfloat16*)(S + OFF_FFH);
    __nv_bfloat16* ffl  = (__nv_bfloat16*)(S + OFF_FFL);
    __nv_bfloat16* wqkvh = (__nv_bfloat16*)(S + OFF_WQKVH);
    __nv_bfloat16* wqkvl = (__nv_bfloat16*)(S + OFF_WQKVL);
    __nv_bfloat16* wph = (__nv_bfloat16*)(S + OFF_WPH);
    __nv_bfloat16* wpl = (__nv_bfloat16*)(S + OFF_WPL);
    __nv_bfloat16* w1h = (__nv_bfloat16*)(S + OFF_W1H);
    __nv_bfloat16* w1l = (__nv_bfloat16*)(S + OFF_W1L);
    __nv_bfloat16* w2h = (__nv_bfloat16*)(S + OFF_W2H);
    __nv_bfloat16* w2l = (__nv_bfloat16*)(S + OFF_W2L);
    float* biasC = (float*)(S + OFF_BIASC);

    cudaFuncSetAttribute(attn_tc, cudaFuncAttributeMaxDynamicSharedMemorySize, ATTN_SMEM);
    cudaFuncSetAttribute(gemm_tc, cudaFuncAttributeMaxDynamicSharedMemorySize, GEMM_SMEM);

    // 1: bias concat
    bias_concat_kernel<<<3, 1024>>>(bq, bk, bv, biasC);
    // 2: ALL weight conversions in one launch
    wconv_all<<<3072, 256>>>(Wq, Wk, Wv, Wp, W1, W2,
                             wqkvh, wqkvl, wph, wpl, w1h, w1l, w2h, w2l);
    // 3: LN1
    ln_kernel<<<NROWS, 256>>>(x, g1, be1, ln1h, ln1l);

    dim3 gQKV(24, 32);
    dim3 gQ(8, 32);
    dim3 gF1(32, 32);
    // 4: QKV
    gemm_tc<<<gQKV, 256, GEMM_SMEM>>>(ln1h, ln1l, wqkvh, wqkvl, biasC, nullptr,
                                      nullptr, qhB, qlB, 1024, 1024, 0, 1);
    // 5: attention
    attn_tc<<<dim3(TSEQ / 128, 4 * NHEADS), 256, ATTN_SMEM>>>(qhB, qlB, khB, klB, vhB, vlB, atth, attl);
    // 6: proj (ncu -s 5 -c 1 lands here)
    gemm_tc<<<gQ, 256, GEMM_SMEM>>>(atth, attl, wph, wpl, bp, x, yb, nullptr, nullptr, 1024, 1024, 0, 0);
    // 7: LN2
    ln_kernel<<<NROWS, 256>>>(yb, g2, be2, ln2h, ln2l);
    // 8: FF1
    gemm_tc<<<gF1, 256, GEMM_SMEM>>>(ln2h, ln2l, w1h, w1l, b1, nullptr, nullptr, ffh, ffl, 1024, 4096, 1, 0);
    // 9: FF2
    gemm_tc<<<gQ, 256, GEMM_SMEM>>>(ffh, ffl, w2h, w2l, b2, yb, out, nullptr, nullptr, 4096, 1024, 0, 0);
}